// round 4
// baseline (speedup 1.0000x reference)
#include <cuda_runtime.h>
#include <math.h>

// ============================================================================
// ResponseAttention: out = softmax( (Q·K^T + Q·Kr^T)/sqrt(H) ) · V
// with Q = x·Wq^T + bq, K = x·Wk^T + bk, Kr = rp·Wk^T + bk, V = x·Wv^T + bv.
// Key identity: K + Kr = (x+rp)·Wk^T + 2·bk  ->  scores = Qs · K'^T with
// Qs = (x·Wq^T + bq)/sqrt(H).  Everything fp32 (precision gate: 1e-3).
// B=4, S=4096, H=512.
// ============================================================================

#define TM 128
#define TN 128
#define TK 16
#define NTHREADS 256

// Scratch (alloc-free rule: __device__ globals)
__device__ float g_Q[16384 * 512];                 // 32 MB
__device__ float g_K[16384 * 512];                 // 32 MB  (K + Kr combined)
__device__ float g_V[16384 * 512];                 // 32 MB
__device__ float g_S[4ULL * 4096 * 4096];          // 256 MB scores

// ---- packed f32x2 helpers (Blackwell FFMA2: 2x fp32 FMA rate) ----
__device__ __forceinline__ unsigned long long pack2(float lo, float hi) {
    unsigned long long r;
    asm("mov.b64 %0, {%1, %2};" : "=l"(r) : "f"(lo), "f"(hi));
    return r;
}
__device__ __forceinline__ void unpack2(unsigned long long v, float& lo, float& hi) {
    asm("mov.b64 {%0, %1}, %2;" : "=f"(lo), "=f"(hi) : "l"(v));
}
__device__ __forceinline__ unsigned long long ffma2(unsigned long long a,
                                                    unsigned long long b,
                                                    unsigned long long c) {
    unsigned long long d;
    asm("fma.rn.f32x2 %0, %1, %2, %3;" : "=l"(d) : "l"(a), "l"(b), "l"(c));
    return d;
}

// ============================================================================
// Generic fp32 GEMM, C = alpha * (A op(B)) + bcoef * bias[n]
//   BT=true : B is [N,K] row-major (NT gemm, C[m,n] = sum_k A[m,k] B[n,k])
//   BT=false: B is [K,N] row-major (NN gemm, C[m,n] = sum_k A[m,k] B[k,n])
//   ADD_A2  : A tile is (A + A2) elementwise (fuses x+relative_pos)
// grid.z batches with strides sA/sB/sC (elements).
// REQUIRES: M%128==0, N%128==0, K%16==0 (true for all uses here).
// ============================================================================
template <bool BT, bool ADD_A2>
__global__ __launch_bounds__(NTHREADS, 2)
void gemm_f32x2(const float* __restrict__ Ag, const float* __restrict__ A2g,
                const float* __restrict__ Bg, const float* __restrict__ biasg,
                float* __restrict__ Cg,
                int M, int N, int K,
                size_t sA, size_t sB, size_t sC,
                float alpha, float bcoef)
{
    const float* A  = Ag + (size_t)blockIdx.z * sA;
    const float* A2 = ADD_A2 ? (A2g + (size_t)blockIdx.z * sA) : (const float*)0;
    const float* B  = Bg + (size_t)blockIdx.z * sB;
    float*       C  = Cg + (size_t)blockIdx.z * sC;

    __shared__ __align__(16) float As[2][TK][TM + 4];
    __shared__ __align__(16) float Bs[2][TK][TN + 4];

    const int t  = threadIdx.x;
    const int m0 = blockIdx.y * TM;
    const int n0 = blockIdx.x * TN;

    // transposed-store load mapping (A and BT-B): 128 rows x 4 float4 along K
    const int lrow = t >> 2;     // 0..63 (+64 for second half)
    const int lc4  = t & 3;      // which float4 along K
    // NN-B load mapping: 16 k-rows x 32 float4 along N
    const int bkr  = t >> 5;     // 0..7 (+8)
    const int bn4  = t & 31;

    // compute mapping: 8x8 micro-tile per thread
    const int mreg = (t >> 4) * 8;
    const int nreg = (t & 15) * 8;

    unsigned long long acc[8][4];
#pragma unroll
    for (int i = 0; i < 8; i++)
#pragma unroll
        for (int j = 0; j < 4; j++) acc[i][j] = 0ULL;

    float4 va[2], vb[2];

    auto ldg_tile = [&](int kt) {
#pragma unroll
        for (int h = 0; h < 2; h++) {
            const int row = lrow + h * 64;
            float4 v = *(const float4*)(A + (size_t)(m0 + row) * K + (kt + lc4 * 4));
            if (ADD_A2) {
                const float4 v2 = *(const float4*)(A2 + (size_t)(m0 + row) * K + (kt + lc4 * 4));
                v.x += v2.x; v.y += v2.y; v.z += v2.z; v.w += v2.w;
            }
            va[h] = v;
        }
        if (BT) {
#pragma unroll
            for (int h = 0; h < 2; h++) {
                const int row = lrow + h * 64;
                vb[h] = *(const float4*)(B + (size_t)(n0 + row) * K + (kt + lc4 * 4));
            }
        } else {
#pragma unroll
            for (int h = 0; h < 2; h++) {
                const int krow = bkr + h * 8;
                vb[h] = *(const float4*)(B + (size_t)(kt + krow) * N + (n0 + bn4 * 4));
            }
        }
    };

    auto sts_tile = [&](int st) {
#pragma unroll
        for (int h = 0; h < 2; h++) {
            const int row = lrow + h * 64;
            As[st][lc4 * 4 + 0][row] = va[h].x;
            As[st][lc4 * 4 + 1][row] = va[h].y;
            As[st][lc4 * 4 + 2][row] = va[h].z;
            As[st][lc4 * 4 + 3][row] = va[h].w;
        }
        if (BT) {
#pragma unroll
            for (int h = 0; h < 2; h++) {
                const int row = lrow + h * 64;
                Bs[st][lc4 * 4 + 0][row] = vb[h].x;
                Bs[st][lc4 * 4 + 1][row] = vb[h].y;
                Bs[st][lc4 * 4 + 2][row] = vb[h].z;
                Bs[st][lc4 * 4 + 3][row] = vb[h].w;
            }
        } else {
#pragma unroll
            for (int h = 0; h < 2; h++) {
                const int krow = bkr + h * 8;
                *(float4*)&Bs[st][krow][bn4 * 4] = vb[h];
            }
        }
    };

    // prologue
    ldg_tile(0);
    sts_tile(0);
    __syncthreads();

    int s = 0;
    for (int kt = 0; kt < K; kt += TK) {
        const bool has_next = (kt + TK) < K;
        if (has_next) ldg_tile(kt + TK);

#pragma unroll
        for (int k = 0; k < TK; k++) {
            const float4 a0 = *(const float4*)&As[s][k][mreg];
            const float4 a1 = *(const float4*)&As[s][k][mreg + 4];
            const float4 b0 = *(const float4*)&Bs[s][k][nreg];
            const float4 b1 = *(const float4*)&Bs[s][k][nreg + 4];
            unsigned long long bb0 = pack2(b0.x, b0.y);
            unsigned long long bb1 = pack2(b0.z, b0.w);
            unsigned long long bb2 = pack2(b1.x, b1.y);
            unsigned long long bb3 = pack2(b1.z, b1.w);
            const float av[8] = {a0.x, a0.y, a0.z, a0.w, a1.x, a1.y, a1.z, a1.w};
#pragma unroll
            for (int i = 0; i < 8; i++) {
                const unsigned long long aa = pack2(av[i], av[i]);
                acc[i][0] = ffma2(aa, bb0, acc[i][0]);
                acc[i][1] = ffma2(aa, bb1, acc[i][1]);
                acc[i][2] = ffma2(aa, bb2, acc[i][2]);
                acc[i][3] = ffma2(aa, bb3, acc[i][3]);
            }
        }

        if (has_next) sts_tile(s ^ 1);
        __syncthreads();
        s ^= 1;
    }

    // epilogue: alpha scale + bias
    float bl[8];
    if (biasg) {
#pragma unroll
        for (int j = 0; j < 8; j++) bl[j] = bcoef * __ldg(&biasg[n0 + nreg + j]);
    } else {
#pragma unroll
        for (int j = 0; j < 8; j++) bl[j] = 0.0f;
    }

#pragma unroll
    for (int i = 0; i < 8; i++) {
        float o[8];
#pragma unroll
        for (int j = 0; j < 4; j++) unpack2(acc[i][j], o[2 * j], o[2 * j + 1]);
        float4 w0, w1;
        w0.x = alpha * o[0] + bl[0];
        w0.y = alpha * o[1] + bl[1];
        w0.z = alpha * o[2] + bl[2];
        w0.w = alpha * o[3] + bl[3];
        w1.x = alpha * o[4] + bl[4];
        w1.y = alpha * o[5] + bl[5];
        w1.z = alpha * o[6] + bl[6];
        w1.w = alpha * o[7] + bl[7];
        float* cp = C + (size_t)(m0 + mreg + i) * N + (n0 + nreg);
        *(float4*)cp       = w0;
        *(float4*)(cp + 4) = w1;
    }
}

// ============================================================================
// Row softmax over n=4096, one block (256 threads) per row, all in registers.
// ============================================================================
__global__ void softmax_rows(float* __restrict__ S)
{
    const int n = 4096;
    float* p = S + (size_t)blockIdx.x * n;
    const int t = threadIdx.x;

    float4 v[4];
#pragma unroll
    for (int i = 0; i < 4; i++) v[i] = *(const float4*)(p + (size_t)(i * 256 + t) * 4);

    __shared__ float redm[8];
    __shared__ float reds[8];

    float mx = -3.4e38f;
#pragma unroll
    for (int i = 0; i < 4; i++)
        mx = fmaxf(mx, fmaxf(fmaxf(v[i].x, v[i].y), fmaxf(v[i].z, v[i].w)));
#pragma unroll
    for (int o = 16; o; o >>= 1) mx = fmaxf(mx, __shfl_xor_sync(0xffffffffu, mx, o));
    if ((t & 31) == 0) redm[t >> 5] = mx;
    __syncthreads();
    float m = redm[0];
#pragma unroll
    for (int i = 1; i < 8; i++) m = fmaxf(m, redm[i]);

    float sum = 0.0f;
#pragma unroll
    for (int i = 0; i < 4; i++) {
        v[i].x = __expf(v[i].x - m);
        v[i].y = __expf(v[i].y - m);
        v[i].z = __expf(v[i].z - m);
        v[i].w = __expf(v[i].w - m);
        sum += (v[i].x + v[i].y) + (v[i].z + v[i].w);
    }
#pragma unroll
    for (int o = 16; o; o >>= 1) sum += __shfl_xor_sync(0xffffffffu, sum, o);
    if ((t & 31) == 0) reds[t >> 5] = sum;
    __syncthreads();
    float stot = 0.0f;
#pragma unroll
    for (int i = 0; i < 8; i++) stot += reds[i];
    const float inv = 1.0f / stot;

#pragma unroll
    for (int i = 0; i < 4; i++) {
        v[i].x *= inv; v[i].y *= inv; v[i].z *= inv; v[i].w *= inv;
        *(float4*)(p + (size_t)(i * 256 + t) * 4) = v[i];
    }
}

// ============================================================================
// kernel_launch
// inputs: x, relative_pos, Wq, bq, Wk, bk, Wv, bv  (all fp32)
// output: [4, 4096, 512] fp32
// ============================================================================
extern "C" void kernel_launch(void* const* d_in, const int* in_sizes, int n_in,
                              void* d_out, int out_size)
{
    (void)in_sizes; (void)n_in; (void)out_size;
    const float* x  = (const float*)d_in[0];
    const float* rp = (const float*)d_in[1];
    const float* Wq = (const float*)d_in[2];
    const float* bq = (const float*)d_in[3];
    const float* Wk = (const float*)d_in[4];
    const float* bk = (const float*)d_in[5];
    const float* Wv = (const float*)d_in[6];
    const float* bv = (const float*)d_in[7];
    float* out = (float*)d_out;

    float *Q, *Kp, *V, *S;
    cudaGetSymbolAddress((void**)&Q,  g_Q);
    cudaGetSymbolAddress((void**)&Kp, g_K);
    cudaGetSymbolAddress((void**)&V,  g_V);
    cudaGetSymbolAddress((void**)&S,  g_S);

    const int B = 4, Sq = 4096, H = 512;
    const int Mtok = B * Sq;                   // 16384
    const float sc = (float)(1.0 / sqrt((double)H));

    const dim3 blk(NTHREADS);

    // --- projections: C[16384,512] = X[16384,512] · W[512,512]^T + b ---
    // Q pre-scaled by 1/sqrt(H); K' = (x+rp)·Wk^T + 2·bk; V plain.
    gemm_f32x2<true, false><<<dim3(H / TN, Mtok / TM, 1), blk>>>(
        x, (const float*)0, Wq, bq, Q, Mtok, H, H, 0, 0, 0, sc, sc);
    gemm_f32x2<true, true><<<dim3(H / TN, Mtok / TM, 1), blk>>>(
        x, rp, Wk, bk, Kp, Mtok, H, H, 0, 0, 0, 1.0f, 2.0f);
    gemm_f32x2<true, false><<<dim3(H / TN, Mtok / TM, 1), blk>>>(
        x, (const float*)0, Wv, bv, V, Mtok, H, H, 0, 0, 0, 1.0f, 1.0f);

    // --- scores: S[b] = Qs[b] · K'[b]^T, batched over grid.z ---
    gemm_f32x2<true, false><<<dim3(Sq / TN, Sq / TM, B), blk>>>(
        Q, (const float*)0, Kp, (const float*)0, S,
        Sq, Sq, H, (size_t)Sq * H, (size_t)Sq * H, (size_t)Sq * Sq, 1.0f, 0.0f);

    // --- softmax over rows ---
    softmax_rows<<<B * Sq, 256>>>(S);

    // --- output: O[b] = P[b] · V[b]  (NN gemm) ---
    gemm_f32x2<false, false><<<dim3(H / TN, Sq / TM, B), blk>>>(
        S, (const float*)0, V, (const float*)0, out,
        Sq, H, Sq, (size_t)Sq * Sq, (size_t)Sq * H, (size_t)Sq * H, 1.0f, 0.0f);
}

// round 6
// speedup vs baseline: 2.1804x; 2.1804x over previous
#include <cuda_runtime.h>
#include <cuda_fp16.h>
#include <math.h>
#include <stdint.h>

// ============================================================================
// ResponseAttention via mma.sync (m16n8k16 fp16) with Ozaki 2-term fp16 split.
//   scores = Qs · K'^T, Qs=(x·Wq^T+bq)/sqrt(H), K'=(x+rp)·Wk^T+2bk
//   out    = softmax(scores) · V   (V stored transposed so P·V is NT too)
// Each fp32 operand X is split X ≈ Xhi + Xlo (fp16 each, 22 mantissa bits
// combined). Each GEMM computes hi·hi + hi·lo + lo·hi in fp32 accumulators:
// per-product error ~2^-21 -> rel_err ~1e-5, far under the 1e-3 gate.
// NOTE: tcgen05 is NOT available (harness compiles via compute_103 virtual
// arch, no 'a' feature set) — mma.sync is the only tensor-core path.
// B=4, S=4096, H=512.
// ============================================================================

#define BM 128
#define BN 128
#define BK 32
#define NSTAGE 3
#define NTH 256

#define TOK 16384
#define HD  512
#define SEQ 4096
#define NB  4

// smem: rows of 32 fp16 padded to 40 (80 B) -> conflict-free ldmatrix
#define ROWB 80
#define ST_AH 0
#define ST_AL (128 * ROWB)
#define ST_BH (2 * 128 * ROWB)
#define ST_BL (3 * 128 * ROWB)
#define STAGE_BYTES (4 * 128 * ROWB)            // 40960
#define SMEM_BYTES  (NSTAGE * STAGE_BYTES)      // 122880

// ---------------------------- scratch ------------------------------------
__device__ __half g_xsh[TOK * HD], g_xsl[TOK * HD];
__device__ __half g_xrh[TOK * HD], g_xrl[TOK * HD];
__device__ __half g_wqh[HD * HD], g_wql[HD * HD];
__device__ __half g_wkh[HD * HD], g_wkl[HD * HD];
__device__ __half g_wvh[HD * HD], g_wvl[HD * HD];
__device__ __half g_qh[TOK * HD], g_ql[TOK * HD];
__device__ __half g_kh[TOK * HD], g_kl[TOK * HD];
__device__ __half g_vth[TOK * HD], g_vtl[TOK * HD];
__device__ float  g_S[(size_t)NB * SEQ * SEQ];
__device__ __half g_ph[(size_t)NB * SEQ * SEQ], g_pl[(size_t)NB * SEQ * SEQ];

// ---------------------------- helpers ------------------------------------
__device__ __forceinline__ uint32_t smem_u32(const void* p) {
    uint32_t a;
    asm("{ .reg .u64 t; cvta.to.shared.u64 t, %1; cvt.u32.u64 %0, t; }"
        : "=r"(a) : "l"(p));
    return a;
}
__device__ __forceinline__ void cp16(uint32_t s, const void* g) {
    asm volatile("cp.async.cg.shared.global [%0], [%1], 16;" :: "r"(s), "l"(g));
}
#define CP_COMMIT() asm volatile("cp.async.commit_group;")
#define CP_WAIT(n)  asm volatile("cp.async.wait_group %0;" :: "n"(n))

__device__ __forceinline__ void ldsm4(uint32_t r[4], uint32_t addr) {
    asm volatile("ldmatrix.sync.aligned.m8n8.x4.shared.b16 {%0,%1,%2,%3}, [%4];"
        : "=r"(r[0]), "=r"(r[1]), "=r"(r[2]), "=r"(r[3]) : "r"(addr));
}
__device__ __forceinline__ void mma16816(float acc[4], const uint32_t a[4],
                                         const uint32_t b0, const uint32_t b1) {
    asm volatile(
        "mma.sync.aligned.m16n8k16.row.col.f32.f16.f16.f32 "
        "{%0,%1,%2,%3}, {%4,%5,%6,%7}, {%8,%9}, {%0,%1,%2,%3};"
        : "+f"(acc[0]), "+f"(acc[1]), "+f"(acc[2]), "+f"(acc[3])
        : "r"(a[0]), "r"(a[1]), "r"(a[2]), "r"(a[3]), "r"(b0), "r"(b1));
}

// ============================================================================
// NT GEMM, C[M,N] = A[M,K] * B[N,K]^T, A/B as (hi, lo) fp16 pairs, fp32 accum.
// MODE 0: O1 = fp32 C (row-major, batch stride sO)
// MODE 1: O1/O2 = fp16 hi/lo of (alpha*C + bcoef*bias[n]), row-major [M,N]
// MODE 2: like 1 but transposed per 4096-row batch: O[(m>>12)*HD + n][m&4095]
// ============================================================================
template <int MODE>
__global__ __launch_bounds__(NTH, 1)
void mma_nt(const __half* __restrict__ AHg, const __half* __restrict__ ALg,
            const __half* __restrict__ BHg, const __half* __restrict__ BLg,
            const float* __restrict__ bias, float alpha, float bcoef,
            void* __restrict__ O1, void* __restrict__ O2,
            int N, int K, size_t sA, size_t sB, size_t sO)
{
    extern __shared__ char smem[];
    const uint32_t sbase = smem_u32(smem);

    const int tid  = threadIdx.x;
    const int lane = tid & 31;
    const int wid  = tid >> 5;
    const int m0 = blockIdx.y * BM;
    const int n0 = blockIdx.x * BN;

    const __half* AH = AHg + (size_t)blockIdx.z * sA;
    const __half* AL = ALg + (size_t)blockIdx.z * sA;
    const __half* BH = BHg + (size_t)blockIdx.z * sB;
    const __half* BL = BLg + (size_t)blockIdx.z * sB;

    // cp.async fill of one 128x32 (x4 matrices) stage
    auto fill = [&](int stg, int kt) {
        const int kc = kt * BK;
        const uint32_t sb = sbase + stg * STAGE_BYTES;
#pragma unroll
        for (int j = 0; j < 2; j++) {
            const int idx = tid + NTH * j;
            const int r  = idx >> 2;
            const int ch = idx & 3;
            const uint32_t so = (uint32_t)(r * ROWB + ch * 16);
            const size_t gao = (size_t)(m0 + r) * K + kc + ch * 8;
            const size_t gbo = (size_t)(n0 + r) * K + kc + ch * 8;
            cp16(sb + ST_AH + so, AH + gao);
            cp16(sb + ST_AL + so, AL + gao);
            cp16(sb + ST_BH + so, BH + gbo);
            cp16(sb + ST_BL + so, BL + gbo);
        }
        CP_COMMIT();
    };

    // warp tiling: 2 (M) x 4 (N) warps; warp tile 64x32
    const int warpM = wid & 1;
    const int warpN = wid >> 1;

    // ldmatrix lane address components
    const int a_row = warpM * 64 + (lane & 15);
    const int a_kad = (lane >> 4) << 3;                        // 0 / 8
    const int b_row = warpN * 32 + (lane & 7) + ((lane >> 4) << 3);
    const int b_kad = ((lane >> 3) & 1) << 3;                  // 0 / 8

    float acc[4][4][4];
#pragma unroll
    for (int mi = 0; mi < 4; mi++)
#pragma unroll
        for (int ni = 0; ni < 4; ni++)
#pragma unroll
            for (int r = 0; r < 4; r++) acc[mi][ni][r] = 0.0f;

    const int KT = K / BK;

    fill(0, 0);
    fill(1, 1);

    for (int kt = 0; kt < KT; kt++) {
        CP_WAIT(1);
        __syncthreads();
        const uint32_t sb = sbase + (kt % NSTAGE) * STAGE_BYTES;
        if (kt + NSTAGE - 1 < KT) fill((kt + NSTAGE - 1) % NSTAGE, kt + NSTAGE - 1);

#pragma unroll
        for (int ks = 0; ks < 2; ks++) {
            const int ko = ks * 16;
            uint32_t aH[4][4], aL[4][4];
#pragma unroll
            for (int mi = 0; mi < 4; mi++) {
                const uint32_t ad = sb + ST_AH
                    + (uint32_t)((a_row + mi * 16) * ROWB + (ko + a_kad) * 2);
                ldsm4(aH[mi], ad);
                ldsm4(aL[mi], ad + (ST_AL - ST_AH));
            }
            uint32_t bHf[2][4], bLf[2][4];
#pragma unroll
            for (int nf = 0; nf < 2; nf++) {
                const uint32_t bd = sb + ST_BH
                    + (uint32_t)((b_row + nf * 16) * ROWB + (ko + b_kad) * 2);
                ldsm4(bHf[nf], bd);
                ldsm4(bLf[nf], bd + (ST_BL - ST_BH));
            }
#pragma unroll
            for (int mi = 0; mi < 4; mi++) {
#pragma unroll
                for (int ni = 0; ni < 4; ni++) {
                    const uint32_t* bh = &bHf[ni >> 1][(ni & 1) * 2];
                    const uint32_t* bl = &bLf[ni >> 1][(ni & 1) * 2];
                    mma16816(acc[mi][ni], aH[mi], bh[0], bh[1]);   // hi*hi
                    mma16816(acc[mi][ni], aH[mi], bl[0], bl[1]);   // hi*lo
                    mma16816(acc[mi][ni], aL[mi], bh[0], bh[1]);   // lo*hi
                }
            }
        }
    }

    // ---------------------------- epilogue -------------------------------
    const int mbase = m0 + warpM * 64;
    const int nbase = n0 + warpN * 32;
    const int rq = lane >> 2;            // 0..7
    const int cq = (lane & 3) * 2;       // 0,2,4,6

#pragma unroll
    for (int mi = 0; mi < 4; mi++) {
#pragma unroll
        for (int ni = 0; ni < 4; ni++) {
            const int mrow = mbase + mi * 16 + rq;
            const int ncol = nbase + ni * 8 + cq;
            const float* a4 = acc[mi][ni];

            if (MODE == 0) {
                float* o = (float*)O1 + (size_t)blockIdx.z * sO;
                float2 v0 = make_float2(a4[0], a4[1]);
                float2 v1 = make_float2(a4[2], a4[3]);
                *(float2*)(o + (size_t)mrow * N + ncol)       = v0;
                *(float2*)(o + (size_t)(mrow + 8) * N + ncol) = v1;
            } else {
                const float b0 = bcoef * __ldg(&bias[ncol]);
                const float b1 = bcoef * __ldg(&bias[ncol + 1]);
#pragma unroll
                for (int h = 0; h < 2; h++) {
                    const int m = mrow + h * 8;
                    const float v0 = alpha * a4[2 * h]     + b0;
                    const float v1 = alpha * a4[2 * h + 1] + b1;
                    const __half h0 = __float2half(v0);
                    const __half h1 = __float2half(v1);
                    const __half l0 = __float2half(v0 - __half2float(h0));
                    const __half l1 = __float2half(v1 - __half2float(h1));
                    if (MODE == 1) {
                        __half* oh = (__half*)O1 + (size_t)m * N + ncol;
                        __half* ol = (__half*)O2 + (size_t)m * N + ncol;
                        *(__half2*)oh = __halves2half2(h0, h1);
                        *(__half2*)ol = __halves2half2(l0, l1);
                    } else {  // MODE 2: transposed V store Vt[(b*HD+n)][s]
                        const int bb = m >> 12;
                        const int ss = m & 4095;
                        __half* oh = (__half*)O1;
                        __half* ol = (__half*)O2;
                        const size_t i0 = ((size_t)bb * HD + ncol) * SEQ + ss;
                        oh[i0]       = h0;
                        ol[i0]       = l0;
                        oh[i0 + SEQ] = h1;    // ncol+1
                        ol[i0 + SEQ] = l1;
                    }
                }
            }
        }
    }
}

// ============================================================================
// split kernel: v = a[i] (+ b[i]); hi = fp16(v); lo = fp16(v - hi)
// ============================================================================
__global__ void split_kernel(const float* __restrict__ a, const float* __restrict__ b,
                             __half* __restrict__ hi, __half* __restrict__ lo, int n)
{
    const int i = (blockIdx.x * blockDim.x + threadIdx.x) * 4;
    if (i >= n) return;
    float4 v = *(const float4*)(a + i);
    if (b) {
        const float4 u = *(const float4*)(b + i);
        v.x += u.x; v.y += u.y; v.z += u.z; v.w += u.w;
    }
    const __half h0 = __float2half(v.x), h1 = __float2half(v.y);
    const __half h2 = __float2half(v.z), h3 = __float2half(v.w);
    const __half l0 = __float2half(v.x - __half2float(h0));
    const __half l1 = __float2half(v.y - __half2float(h1));
    const __half l2 = __float2half(v.z - __half2float(h2));
    const __half l3 = __float2half(v.w - __half2float(h3));
    *(__half2*)(hi + i)     = __halves2half2(h0, h1);
    *(__half2*)(hi + i + 2) = __halves2half2(h2, h3);
    *(__half2*)(lo + i)     = __halves2half2(l0, l1);
    *(__half2*)(lo + i + 2) = __halves2half2(l2, l3);
}

// ============================================================================
// Row softmax over n=4096, emits P as fp16 hi/lo split.
// ============================================================================
__global__ void softmax_rows(const float* __restrict__ S,
                             __half* __restrict__ ph, __half* __restrict__ pl)
{
    const int n = 4096;
    const size_t base = (size_t)blockIdx.x * n;
    const float* p = S + base;
    const int t = threadIdx.x;

    float4 v[4];
#pragma unroll
    for (int i = 0; i < 4; i++) v[i] = *(const float4*)(p + (size_t)(i * 256 + t) * 4);

    __shared__ float redm[8];
    __shared__ float reds[8];

    float mx = -3.4e38f;
#pragma unroll
    for (int i = 0; i < 4; i++)
        mx = fmaxf(mx, fmaxf(fmaxf(v[i].x, v[i].y), fmaxf(v[i].z, v[i].w)));
#pragma unroll
    for (int o = 16; o; o >>= 1) mx = fmaxf(mx, __shfl_xor_sync(0xffffffffu, mx, o));
    if ((t & 31) == 0) redm[t >> 5] = mx;
    __syncthreads();
    float m = redm[0];
#pragma unroll
    for (int i = 1; i < 8; i++) m = fmaxf(m, redm[i]);

    float sum = 0.0f;
#pragma unroll
    for (int i = 0; i < 4; i++) {
        v[i].x = __expf(v[i].x - m);
        v[i].y = __expf(v[i].y - m);
        v[i].z = __expf(v[i].z - m);
        v[i].w = __expf(v[i].w - m);
        sum += (v[i].x + v[i].y) + (v[i].z + v[i].w);
    }
#pragma unroll
    for (int o = 16; o; o >>= 1) sum += __shfl_xor_sync(0xffffffffu, sum, o);
    if ((t & 31) == 0) reds[t >> 5] = sum;
    __syncthreads();
    float stot = 0.0f;
#pragma unroll
    for (int i = 0; i < 8; i++) stot += reds[i];
    const float inv = 1.0f / stot;

#pragma unroll
    for (int i = 0; i < 4; i++) {
        const int idx = (i * 256 + t) * 4;
        const float p0 = v[i].x * inv, p1 = v[i].y * inv;
        const float p2 = v[i].z * inv, p3 = v[i].w * inv;
        const __half h0 = __float2half(p0), h1 = __float2half(p1);
        const __half h2 = __float2half(p2), h3 = __float2half(p3);
        const __half l0 = __float2half(p0 - __half2float(h0));
        const __half l1 = __float2half(p1 - __half2float(h1));
        const __half l2 = __float2half(p2 - __half2float(h2));
        const __half l3 = __float2half(p3 - __half2float(h3));
        *(__half2*)(ph + base + idx)     = __halves2half2(h0, h1);
        *(__half2*)(ph + base + idx + 2) = __halves2half2(h2, h3);
        *(__half2*)(pl + base + idx)     = __halves2half2(l0, l1);
        *(__half2*)(pl + base + idx + 2) = __halves2half2(l2, l3);
    }
}

// ============================================================================
// kernel_launch
// ============================================================================
extern "C" void kernel_launch(void* const* d_in, const int* in_sizes, int n_in,
                              void* d_out, int out_size)
{
    (void)in_sizes; (void)n_in; (void)out_size;
    const float* x  = (const float*)d_in[0];
    const float* rp = (const float*)d_in[1];
    const float* Wq = (const float*)d_in[2];
    const float* bq = (const float*)d_in[3];
    const float* Wk = (const float*)d_in[4];
    const float* bk = (const float*)d_in[5];
    const float* Wv = (const float*)d_in[6];
    const float* bv = (const float*)d_in[7];
    float* out = (float*)d_out;

    __half *xsh, *xsl, *xrh, *xrl, *wqh, *wql, *wkh, *wkl, *wvh, *wvl;
    __half *qh, *ql, *kh, *kl, *vth, *vtl, *ph, *pl;
    float* S;
    cudaGetSymbolAddress((void**)&xsh, g_xsh); cudaGetSymbolAddress((void**)&xsl, g_xsl);
    cudaGetSymbolAddress((void**)&xrh, g_xrh); cudaGetSymbolAddress((void**)&xrl, g_xrl);
    cudaGetSymbolAddress((void**)&wqh, g_wqh); cudaGetSymbolAddress((void**)&wql, g_wql);
    cudaGetSymbolAddress((void**)&wkh, g_wkh); cudaGetSymbolAddress((void**)&wkl, g_wkl);
    cudaGetSymbolAddress((void**)&wvh, g_wvh); cudaGetSymbolAddress((void**)&wvl, g_wvl);
    cudaGetSymbolAddress((void**)&qh,  g_qh);  cudaGetSymbolAddress((void**)&ql,  g_ql);
    cudaGetSymbolAddress((void**)&kh,  g_kh);  cudaGetSymbolAddress((void**)&kl,  g_kl);
    cudaGetSymbolAddress((void**)&vth, g_vth); cudaGetSymbolAddress((void**)&vtl, g_vtl);
    cudaGetSymbolAddress((void**)&ph,  g_ph);  cudaGetSymbolAddress((void**)&pl,  g_pl);
    cudaGetSymbolAddress((void**)&S,   g_S);

    cudaFuncSetAttribute(mma_nt<0>, cudaFuncAttributeMaxDynamicSharedMemorySize, SMEM_BYTES);
    cudaFuncSetAttribute(mma_nt<1>, cudaFuncAttributeMaxDynamicSharedMemorySize, SMEM_BYTES);
    cudaFuncSetAttribute(mma_nt<2>, cudaFuncAttributeMaxDynamicSharedMemorySize, SMEM_BYTES);

    const float sc = (float)(1.0 / sqrt((double)HD));

    // --- splits ---
    {
        const int nx = TOK * HD;
        split_kernel<<<nx / 1024, 256>>>(x,  (const float*)0, xsh, xsl, nx);
        split_kernel<<<nx / 1024, 256>>>(x,  rp,              xrh, xrl, nx);
        const int nw = HD * HD;
        split_kernel<<<nw / 1024, 256>>>(Wq, (const float*)0, wqh, wql, nw);
        split_kernel<<<nw / 1024, 256>>>(Wk, (const float*)0, wkh, wkl, nw);
        split_kernel<<<nw / 1024, 256>>>(Wv, (const float*)0, wvh, wvl, nw);
    }

    // --- projections (NT: W is [out,in] row-major = [N,K]) ---
    mma_nt<1><<<dim3(HD / BN, TOK / BM, 1), NTH, SMEM_BYTES>>>(
        xsh, xsl, wqh, wql, bq, sc, sc, qh, ql, HD, HD, 0, 0, 0);
    mma_nt<1><<<dim3(HD / BN, TOK / BM, 1), NTH, SMEM_BYTES>>>(
        xrh, xrl, wkh, wkl, bk, 1.0f, 2.0f, kh, kl, HD, HD, 0, 0, 0);
    mma_nt<2><<<dim3(HD / BN, TOK / BM, 1), NTH, SMEM_BYTES>>>(
        xsh, xsl, wvh, wvl, bv, 1.0f, 1.0f, vth, vtl, HD, HD, 0, 0, 0);

    // --- scores: S[b] = Qs[b] · K'[b]^T (fp32 out) ---
    mma_nt<0><<<dim3(SEQ / BN, SEQ / BM, NB), NTH, SMEM_BYTES>>>(
        qh, ql, kh, kl, (const float*)0, 1.0f, 0.0f, S, (void*)0,
        SEQ, HD, (size_t)SEQ * HD, (size_t)SEQ * HD, (size_t)SEQ * SEQ);

    // --- softmax -> P hi/lo ---
    softmax_rows<<<NB * SEQ, 256>>>(S, ph, pl);

    // --- out: O[b] = P[b] · Vt[b]^T (NT, fp32 out) ---
    mma_nt<0><<<dim3(HD / BN, SEQ / BM, NB), NTH, SMEM_BYTES>>>(
        ph, pl, vth, vtl, (const float*)0, 1.0f, 0.0f, out, (void*)0,
        HD, SEQ, (size_t)SEQ * SEQ, (size_t)HD * SEQ, (size_t)SEQ * HD);
}

// round 7
// speedup vs baseline: 3.1819x; 1.4593x over previous
#include <cuda_runtime.h>
#include <cuda_fp16.h>
#include <math.h>
#include <stdint.h>

// ============================================================================
// ResponseAttention via mma.sync (m16n8k16 fp16), Ozaki split GEMMs.
//   scores = Qs · K'^T, Qs=(x·Wq^T+bq)/sqrt(H), K'=(x+rp)·Wk^T+2bk
//   out    = softmax(scores) · V   (V stored transposed so P·V is NT too)
// Projections use full 2-term split on both operands (3 MMAs).
// Big GEMMs (QK, PV) use asymmetric split: A truncated to fp16 (hi only),
// B kept as hi+lo (2 MMAs): rel_err ~3-5e-4 < 1e-3 gate, 0.72x MMA work,
// smaller smem stage -> 2 CTAs/SM, and the LDS/tensor co-bind is broken.
// tcgen05 unavailable (compute_103 virtual arch) — mma.sync is the path.
// B=4, S=4096, H=512.
// ============================================================================

#define BM 128
#define BN 128
#define BK 32
#define NSTAGE 3
#define NTH 256

#define TOK 16384
#define HD  512
#define SEQ 4096
#define NB  4

// smem: rows of 32 fp16 padded to 40 (80 B) -> conflict-free ldmatrix
#define ROWB 80
#define MATB (128 * ROWB)                       // one 128x32 fp16 matrix: 10240 B

#define SMEM_ALO (NSTAGE * 4 * MATB)            // 122880 (AH AL BH BL)
#define SMEM_NOA (NSTAGE * 3 * MATB)            // 92160  (AH BH BL)

// ---------------------------- scratch ------------------------------------
__device__ __half g_xsh[TOK * HD], g_xsl[TOK * HD];
__device__ __half g_xrh[TOK * HD], g_xrl[TOK * HD];
__device__ __half g_wqh[HD * HD], g_wql[HD * HD];
__device__ __half g_wkh[HD * HD], g_wkl[HD * HD];
__device__ __half g_wvh[HD * HD], g_wvl[HD * HD];
__device__ __half g_qh[TOK * HD];
__device__ __half g_kh[TOK * HD], g_kl[TOK * HD];
__device__ __half g_vth[TOK * HD], g_vtl[TOK * HD];
__device__ float  g_S[(size_t)NB * SEQ * SEQ];
__device__ __half g_ph[(size_t)NB * SEQ * SEQ];

// ---------------------------- helpers ------------------------------------
__device__ __forceinline__ uint32_t smem_u32(const void* p) {
    uint32_t a;
    asm("{ .reg .u64 t; cvta.to.shared.u64 t, %1; cvt.u32.u64 %0, t; }"
        : "=r"(a) : "l"(p));
    return a;
}
__device__ __forceinline__ void cp16(uint32_t s, const void* g) {
    asm volatile("cp.async.cg.shared.global [%0], [%1], 16;" :: "r"(s), "l"(g));
}
#define CP_COMMIT() asm volatile("cp.async.commit_group;")
#define CP_WAIT(n)  asm volatile("cp.async.wait_group %0;" :: "n"(n))

__device__ __forceinline__ void ldsm4(uint32_t r[4], uint32_t addr) {
    asm volatile("ldmatrix.sync.aligned.m8n8.x4.shared.b16 {%0,%1,%2,%3}, [%4];"
        : "=r"(r[0]), "=r"(r[1]), "=r"(r[2]), "=r"(r[3]) : "r"(addr));
}
__device__ __forceinline__ void mma16816(float acc[4], const uint32_t a[4],
                                         const uint32_t b0, const uint32_t b1) {
    asm volatile(
        "mma.sync.aligned.m16n8k16.row.col.f32.f16.f16.f32 "
        "{%0,%1,%2,%3}, {%4,%5,%6,%7}, {%8,%9}, {%0,%1,%2,%3};"
        : "+f"(acc[0]), "+f"(acc[1]), "+f"(acc[2]), "+f"(acc[3])
        : "r"(a[0]), "r"(a[1]), "r"(a[2]), "r"(a[3]), "r"(b0), "r"(b1));
}

// ============================================================================
// NT GEMM, C[M,N] = A[M,K] * B[N,K]^T, fp32 accum.
//   ALO=true : A=(hi,lo), 3 MMAs (hi*hi + hi*lo + lo*hi)
//   ALO=false: A=hi only, 2 MMAs (hi*hi + hi*lo)
// MODE 0: O1 = fp32 C (row-major, batch stride sO)
// MODE 1: O1 (+O2 if non-null) = fp16 hi (/lo) of alpha*C + bcoef*bias[n]
// MODE 2: like 1 but transposed per 4096-row batch: O[(m>>12)*HD + n][m&4095]
// ============================================================================
template <int MODE, bool ALO, int MINB>
__global__ __launch_bounds__(NTH, MINB)
void mma_nt(const __half* __restrict__ AHg, const __half* __restrict__ ALg,
            const __half* __restrict__ BHg, const __half* __restrict__ BLg,
            const float* __restrict__ bias, float alpha, float bcoef,
            void* __restrict__ O1, void* __restrict__ O2,
            int N, int K, size_t sA, size_t sB, size_t sO)
{
    constexpr uint32_t STG   = (ALO ? 4 : 3) * MATB;
    constexpr uint32_t ST_AL = MATB;                      // only if ALO
    constexpr uint32_t ST_BH = (ALO ? 2 : 1) * MATB;
    constexpr uint32_t ST_BL = ST_BH + MATB;

    extern __shared__ char smem[];
    const uint32_t sbase = smem_u32(smem);

    const int tid  = threadIdx.x;
    const int lane = tid & 31;
    const int wid  = tid >> 5;
    const int m0 = blockIdx.y * BM;
    const int n0 = blockIdx.x * BN;

    const __half* AH = AHg + (size_t)blockIdx.z * sA;
    const __half* AL = ALO ? (ALg + (size_t)blockIdx.z * sA) : (const __half*)0;
    const __half* BH = BHg + (size_t)blockIdx.z * sB;
    const __half* BL = BLg + (size_t)blockIdx.z * sB;

    auto fill = [&](int stg, int kt) {
        const int kc = kt * BK;
        const uint32_t sb = sbase + stg * STG;
#pragma unroll
        for (int j = 0; j < 2; j++) {
            const int idx = tid + NTH * j;
            const int r  = idx >> 2;
            const int ch = idx & 3;
            const uint32_t so = (uint32_t)(r * ROWB + ch * 16);
            const size_t gao = (size_t)(m0 + r) * K + kc + ch * 8;
            const size_t gbo = (size_t)(n0 + r) * K + kc + ch * 8;
            cp16(sb + so, AH + gao);
            if (ALO) cp16(sb + ST_AL + so, AL + gao);
            cp16(sb + ST_BH + so, BH + gbo);
            cp16(sb + ST_BL + so, BL + gbo);
        }
        CP_COMMIT();
    };

    // warp tiling: 2 (M) x 4 (N) warps; warp tile 64x32
    const int warpM = wid & 1;
    const int warpN = wid >> 1;

    const int a_row = warpM * 64 + (lane & 15);
    const int a_kad = (lane >> 4) << 3;
    const int b_row = warpN * 32 + (lane & 7) + ((lane >> 4) << 3);
    const int b_kad = ((lane >> 3) & 1) << 3;

    float acc[4][4][4];
#pragma unroll
    for (int mi = 0; mi < 4; mi++)
#pragma unroll
        for (int ni = 0; ni < 4; ni++)
#pragma unroll
            for (int r = 0; r < 4; r++) acc[mi][ni][r] = 0.0f;

    const int KT = K / BK;

    fill(0, 0);
    fill(1, 1);

    for (int kt = 0; kt < KT; kt++) {
        CP_WAIT(1);
        __syncthreads();
        const uint32_t sb = sbase + (kt % NSTAGE) * STG;
        if (kt + NSTAGE - 1 < KT) fill((kt + NSTAGE - 1) % NSTAGE, kt + NSTAGE - 1);

#pragma unroll
        for (int ks = 0; ks < 2; ks++) {
            const int ko = ks * 16;
            uint32_t aH[4][4], aL[4][4];
#pragma unroll
            for (int mi = 0; mi < 4; mi++) {
                const uint32_t ad = sb
                    + (uint32_t)((a_row + mi * 16) * ROWB + (ko + a_kad) * 2);
                ldsm4(aH[mi], ad);
                if (ALO) ldsm4(aL[mi], ad + ST_AL);
            }
            uint32_t bHf[2][4], bLf[2][4];
#pragma unroll
            for (int nf = 0; nf < 2; nf++) {
                const uint32_t bd = sb + ST_BH
                    + (uint32_t)((b_row + nf * 16) * ROWB + (ko + b_kad) * 2);
                ldsm4(bHf[nf], bd);
                ldsm4(bLf[nf], bd + (ST_BL - ST_BH));
            }
#pragma unroll
            for (int mi = 0; mi < 4; mi++) {
#pragma unroll
                for (int ni = 0; ni < 4; ni++) {
                    const uint32_t* bh = &bHf[ni >> 1][(ni & 1) * 2];
                    const uint32_t* bl = &bLf[ni >> 1][(ni & 1) * 2];
                    mma16816(acc[mi][ni], aH[mi], bh[0], bh[1]);   // hi*hi
                    mma16816(acc[mi][ni], aH[mi], bl[0], bl[1]);   // hi*lo
                    if (ALO) mma16816(acc[mi][ni], aL[mi], bh[0], bh[1]); // lo*hi
                }
            }
        }
    }

    // ---------------------------- epilogue -------------------------------
    const int mbase = m0 + warpM * 64;
    const int nbase = n0 + warpN * 32;
    const int rq = lane >> 2;
    const int cq = (lane & 3) * 2;
    const bool emit_lo = (O2 != (void*)0);

#pragma unroll
    for (int mi = 0; mi < 4; mi++) {
#pragma unroll
        for (int ni = 0; ni < 4; ni++) {
            const int mrow = mbase + mi * 16 + rq;
            const int ncol = nbase + ni * 8 + cq;
            const float* a4 = acc[mi][ni];

            if (MODE == 0) {
                float* o = (float*)O1 + (size_t)blockIdx.z * sO;
                *(float2*)(o + (size_t)mrow * N + ncol)       = make_float2(a4[0], a4[1]);
                *(float2*)(o + (size_t)(mrow + 8) * N + ncol) = make_float2(a4[2], a4[3]);
            } else {
                const float b0 = bcoef * __ldg(&bias[ncol]);
                const float b1 = bcoef * __ldg(&bias[ncol + 1]);
#pragma unroll
                for (int h = 0; h < 2; h++) {
                    const int m = mrow + h * 8;
                    const float v0 = alpha * a4[2 * h]     + b0;
                    const float v1 = alpha * a4[2 * h + 1] + b1;
                    const __half h0 = __float2half(v0);
                    const __half h1 = __float2half(v1);
                    if (MODE == 1) {
                        __half* oh = (__half*)O1 + (size_t)m * N + ncol;
                        *(__half2*)oh = __halves2half2(h0, h1);
                        if (emit_lo) {
                            const __half l0 = __float2half(v0 - __half2float(h0));
                            const __half l1 = __float2half(v1 - __half2float(h1));
                            __half* ol = (__half*)O2 + (size_t)m * N + ncol;
                            *(__half2*)ol = __halves2half2(l0, l1);
                        }
                    } else {  // MODE 2: transposed V store Vt[(b*HD+n)][s]
                        const int bb = m >> 12;
                        const int ss = m & 4095;
                        const size_t i0 = ((size_t)bb * HD + ncol) * SEQ + ss;
                        ((__half*)O1)[i0]       = h0;
                        ((__half*)O1)[i0 + SEQ] = h1;
                        if (emit_lo) {
                            const __half l0 = __float2half(v0 - __half2float(h0));
                            const __half l1 = __float2half(v1 - __half2float(h1));
                            ((__half*)O2)[i0]       = l0;
                            ((__half*)O2)[i0 + SEQ] = l1;
                        }
                    }
                }
            }
        }
    }
}

// ============================================================================
// split kernel: v = a[i] (+ b[i]); hi = fp16(v); lo = fp16(v - hi)
// ============================================================================
__global__ void split_kernel(const float* __restrict__ a, const float* __restrict__ b,
                             __half* __restrict__ hi, __half* __restrict__ lo, int n)
{
    const int i = (blockIdx.x * blockDim.x + threadIdx.x) * 4;
    if (i >= n) return;
    float4 v = *(const float4*)(a + i);
    if (b) {
        const float4 u = *(const float4*)(b + i);
        v.x += u.x; v.y += u.y; v.z += u.z; v.w += u.w;
    }
    const __half h0 = __float2half(v.x), h1 = __float2half(v.y);
    const __half h2 = __float2half(v.z), h3 = __float2half(v.w);
    const __half l0 = __float2half(v.x - __half2float(h0));
    const __half l1 = __float2half(v.y - __half2float(h1));
    const __half l2 = __float2half(v.z - __half2float(h2));
    const __half l3 = __float2half(v.w - __half2float(h3));
    *(__half2*)(hi + i)     = __halves2half2(h0, h1);
    *(__half2*)(hi + i + 2) = __halves2half2(h2, h3);
    *(__half2*)(lo + i)     = __halves2half2(l0, l1);
    *(__half2*)(lo + i + 2) = __halves2half2(l2, l3);
}

// ============================================================================
// Row softmax over n=4096, emits P as fp16 (hi only).
// ============================================================================
__global__ void softmax_rows(const float* __restrict__ S, __half* __restrict__ ph)
{
    const int n = 4096;
    const size_t base = (size_t)blockIdx.x * n;
    const float* p = S + base;
    const int t = threadIdx.x;

    float4 v[4];
#pragma unroll
    for (int i = 0; i < 4; i++) v[i] = *(const float4*)(p + (size_t)(i * 256 + t) * 4);

    __shared__ float redm[8];
    __shared__ float reds[8];

    float mx = -3.4e38f;
#pragma unroll
    for (int i = 0; i < 4; i++)
        mx = fmaxf(mx, fmaxf(fmaxf(v[i].x, v[i].y), fmaxf(v[i].z, v[i].w)));
#pragma unroll
    for (int o = 16; o; o >>= 1) mx = fmaxf(mx, __shfl_xor_sync(0xffffffffu, mx, o));
    if ((t & 31) == 0) redm[t >> 5] = mx;
    __syncthreads();
    float m = redm[0];
#pragma unroll
    for (int i = 1; i < 8; i++) m = fmaxf(m, redm[i]);

    float sum = 0.0f;
#pragma unroll
    for (int i = 0; i < 4; i++) {
        v[i].x = __expf(v[i].x - m);
        v[i].y = __expf(v[i].y - m);
        v[i].z = __expf(v[i].z - m);
        v[i].w = __expf(v[i].w - m);
        sum += (v[i].x + v[i].y) + (v[i].z + v[i].w);
    }
#pragma unroll
    for (int o = 16; o; o >>= 1) sum += __shfl_xor_sync(0xffffffffu, sum, o);
    if ((t & 31) == 0) reds[t >> 5] = sum;
    __syncthreads();
    float stot = 0.0f;
#pragma unroll
    for (int i = 0; i < 8; i++) stot += reds[i];
    const float inv = 1.0f / stot;

#pragma unroll
    for (int i = 0; i < 4; i++) {
        const int idx = (i * 256 + t) * 4;
        const __half h0 = __float2half(v[i].x * inv);
        const __half h1 = __float2half(v[i].y * inv);
        const __half h2 = __float2half(v[i].z * inv);
        const __half h3 = __float2half(v[i].w * inv);
        *(__half2*)(ph + base + idx)     = __halves2half2(h0, h1);
        *(__half2*)(ph + base + idx + 2) = __halves2half2(h2, h3);
    }
}

// ============================================================================
// kernel_launch
// ============================================================================
extern "C" void kernel_launch(void* const* d_in, const int* in_sizes, int n_in,
                              void* d_out, int out_size)
{
    (void)in_sizes; (void)n_in; (void)out_size;
    const float* x  = (const float*)d_in[0];
    const float* rp = (const float*)d_in[1];
    const float* Wq = (const float*)d_in[2];
    const float* bq = (const float*)d_in[3];
    const float* Wk = (const float*)d_in[4];
    const float* bk = (const float*)d_in[5];
    const float* Wv = (const float*)d_in[6];
    const float* bv = (const float*)d_in[7];
    float* out = (float*)d_out;

    __half *xsh, *xsl, *xrh, *xrl, *wqh, *wql, *wkh, *wkl, *wvh, *wvl;
    __half *qh, *kh, *kl, *vth, *vtl, *ph;
    float* S;
    cudaGetSymbolAddress((void**)&xsh, g_xsh); cudaGetSymbolAddress((void**)&xsl, g_xsl);
    cudaGetSymbolAddress((void**)&xrh, g_xrh); cudaGetSymbolAddress((void**)&xrl, g_xrl);
    cudaGetSymbolAddress((void**)&wqh, g_wqh); cudaGetSymbolAddress((void**)&wql, g_wql);
    cudaGetSymbolAddress((void**)&wkh, g_wkh); cudaGetSymbolAddress((void**)&wkl, g_wkl);
    cudaGetSymbolAddress((void**)&wvh, g_wvh); cudaGetSymbolAddress((void**)&wvl, g_wvl);
    cudaGetSymbolAddress((void**)&qh,  g_qh);
    cudaGetSymbolAddress((void**)&kh,  g_kh);  cudaGetSymbolAddress((void**)&kl,  g_kl);
    cudaGetSymbolAddress((void**)&vth, g_vth); cudaGetSymbolAddress((void**)&vtl, g_vtl);
    cudaGetSymbolAddress((void**)&ph,  g_ph);
    cudaGetSymbolAddress((void**)&S,   g_S);

    cudaFuncSetAttribute((const void*)mma_nt<1, true, 1>,
                         cudaFuncAttributeMaxDynamicSharedMemorySize, SMEM_ALO);
    cudaFuncSetAttribute((const void*)mma_nt<2, true, 1>,
                         cudaFuncAttributeMaxDynamicSharedMemorySize, SMEM_ALO);
    cudaFuncSetAttribute((const void*)mma_nt<0, false, 2>,
                         cudaFuncAttributeMaxDynamicSharedMemorySize, SMEM_NOA);

    const float sc = (float)(1.0 / sqrt((double)HD));

    // --- splits ---
    {
        const int nx = TOK * HD;
        split_kernel<<<nx / 1024, 256>>>(x,  (const float*)0, xsh, xsl, nx);
        split_kernel<<<nx / 1024, 256>>>(x,  rp,              xrh, xrl, nx);
        const int nw = HD * HD;
        split_kernel<<<nw / 1024, 256>>>(Wq, (const float*)0, wqh, wql, nw);
        split_kernel<<<nw / 1024, 256>>>(Wk, (const float*)0, wkh, wkl, nw);
        split_kernel<<<nw / 1024, 256>>>(Wv, (const float*)0, wvh, wvl, nw);
    }

    // --- projections (3-MMA full split; W is [out,in] row-major = [N,K]) ---
    // Q: hi only (its lo term is dropped downstream anyway).
    mma_nt<1, true, 1><<<dim3(HD / BN, TOK / BM, 1), NTH, SMEM_ALO>>>(
        xsh, xsl, wqh, wql, bq, sc, sc, qh, (void*)0, HD, HD, 0, 0, 0);
    mma_nt<1, true, 1><<<dim3(HD / BN, TOK / BM, 1), NTH, SMEM_ALO>>>(
        xrh, xrl, wkh, wkl, bk, 1.0f, 2.0f, kh, kl, HD, HD, 0, 0, 0);
    mma_nt<2, true, 1><<<dim3(HD / BN, TOK / BM, 1), NTH, SMEM_ALO>>>(
        xsh, xsl, wvh, wvl, bv, 1.0f, 1.0f, vth, vtl, HD, HD, 0, 0, 0);

    // --- scores: S[b] = Qh[b] · K'(hi,lo)[b]^T (2-MMA asymmetric, fp32 out) ---
    mma_nt<0, false, 2><<<dim3(SEQ / BN, SEQ / BM, NB), NTH, SMEM_NOA>>>(
        qh, (const __half*)0, kh, kl, (const float*)0, 1.0f, 0.0f, S, (void*)0,
        SEQ, HD, (size_t)SEQ * HD, (size_t)SEQ * HD, (size_t)SEQ * SEQ);

    // --- softmax -> P (fp16 hi only) ---
    softmax_rows<<<NB * SEQ, 256>>>(S, ph);

    // --- out: O[b] = Ph[b] · Vt(hi,lo)[b]^T (2-MMA asymmetric, fp32 out) ---
    mma_nt<0, false, 2><<<dim3(HD / BN, SEQ / BM, NB), NTH, SMEM_NOA>>>(
        ph, (const __half*)0, vth, vtl, (const float*)0, 1.0f, 0.0f, out, (void*)0,
        HD, SEQ, (size_t)SEQ * SEQ, (size_t)HD * SEQ, (size_t)SEQ * HD);
}

// round 8
// speedup vs baseline: 3.2512x; 1.0218x over previous
#include <cuda_runtime.h>
#include <cuda_fp16.h>
#include <math.h>
#include <stdint.h>

// ============================================================================
// ResponseAttention via mma.sync (m16n8k16 fp16), Ozaki split GEMMs.
//   scores = Qs · K'^T, Qs=(x·Wq^T+bq)/sqrt(H), K'=(x+rp)·Wk^T+2bk
//   out    = softmax(scores) · V   (V stored transposed so P·V is NT too)
// K'/V projections: full 2-term split both operands (3 MMAs).
// Q projection + big GEMMs (QK, PV): asymmetric split, A fp16-hi only
// (2 MMAs) — A-side lo is dropped downstream anyway. rel_err ~4e-4 < 1e-3.
// R8: coalesced V-transpose epilogue via smem; per-batch QK->softmax for S
// L2 residency; merged split launches; last-iter cp.async wait fix.
// tcgen05 unavailable (compute_103 virtual arch) — mma.sync is the path.
// B=4, S=4096, H=512.
// ============================================================================

#define BM 128
#define BN 128
#define BK 32
#define NSTAGE 3
#define NTH 256

#define TOK 16384
#define HD  512
#define SEQ 4096
#define NB  4

// smem: rows of 32 fp16 padded to 40 (80 B) -> conflict-free ldmatrix
#define ROWB 80
#define MATB (128 * ROWB)                       // one 128x32 fp16 matrix: 10240 B

#define SMEM_ALO (NSTAGE * 4 * MATB)            // 122880 (AH AL BH BL)
#define SMEM_NOA (NSTAGE * 3 * MATB)            // 92160  (AH BH BL)

#define TSTR 136                                 // transpose-buffer row stride (halves)

// ---------------------------- scratch ------------------------------------
__device__ __half g_xsh[TOK * HD], g_xsl[TOK * HD];
__device__ __half g_xrh[TOK * HD], g_xrl[TOK * HD];
__device__ __half g_wqh[HD * HD], g_wql[HD * HD];
__device__ __half g_wkh[HD * HD], g_wkl[HD * HD];
__device__ __half g_wvh[HD * HD], g_wvl[HD * HD];
__device__ __half g_qh[TOK * HD];
__device__ __half g_kh[TOK * HD], g_kl[TOK * HD];
__device__ __half g_vth[TOK * HD], g_vtl[TOK * HD];
__device__ float  g_S[(size_t)NB * SEQ * SEQ];
__device__ __half g_ph[(size_t)NB * SEQ * SEQ];

// ---------------------------- helpers ------------------------------------
__device__ __forceinline__ uint32_t smem_u32(const void* p) {
    uint32_t a;
    asm("{ .reg .u64 t; cvta.to.shared.u64 t, %1; cvt.u32.u64 %0, t; }"
        : "=r"(a) : "l"(p));
    return a;
}
__device__ __forceinline__ void cp16(uint32_t s, const void* g) {
    asm volatile("cp.async.cg.shared.global [%0], [%1], 16;" :: "r"(s), "l"(g));
}
#define CP_COMMIT() asm volatile("cp.async.commit_group;")
#define CP_WAIT(n)  asm volatile("cp.async.wait_group %0;" :: "n"(n))

__device__ __forceinline__ void ldsm4(uint32_t r[4], uint32_t addr) {
    asm volatile("ldmatrix.sync.aligned.m8n8.x4.shared.b16 {%0,%1,%2,%3}, [%4];"
        : "=r"(r[0]), "=r"(r[1]), "=r"(r[2]), "=r"(r[3]) : "r"(addr));
}
__device__ __forceinline__ void mma16816(float acc[4], const uint32_t a[4],
                                         const uint32_t b0, const uint32_t b1) {
    asm volatile(
        "mma.sync.aligned.m16n8k16.row.col.f32.f16.f16.f32 "
        "{%0,%1,%2,%3}, {%4,%5,%6,%7}, {%8,%9}, {%0,%1,%2,%3};"
        : "+f"(acc[0]), "+f"(acc[1]), "+f"(acc[2]), "+f"(acc[3])
        : "r"(a[0]), "r"(a[1]), "r"(a[2]), "r"(a[3]), "r"(b0), "r"(b1));
}

// ============================================================================
// NT GEMM, C[M,N] = A[M,K] * B[N,K]^T, fp32 accum.
//   ALO=true : A=(hi,lo), 3 MMAs (hi*hi + hi*lo + lo*hi)
//   ALO=false: A=hi only, 2 MMAs (hi*hi + hi*lo)
// MODE 0: O1 = fp32 C (row-major)
// MODE 1: O1 (+O2 if non-null) = fp16 hi (/lo) of alpha*C + bcoef*bias[n]
// MODE 2: hi/lo fp16, stored TRANSPOSED per 4096-row batch via smem staging:
//         O[(m>>12)*HD + n][m&4095], coalesced 16B row writes.
// ============================================================================
template <int MODE, bool ALO, int MINB>
__global__ __launch_bounds__(NTH, MINB)
void mma_nt(const __half* __restrict__ AHg, const __half* __restrict__ ALg,
            const __half* __restrict__ BHg, const __half* __restrict__ BLg,
            const float* __restrict__ bias, float alpha, float bcoef,
            void* __restrict__ O1, void* __restrict__ O2,
            int N, int K, size_t sA, size_t sB, size_t sO)
{
    constexpr uint32_t STG   = (ALO ? 4 : 3) * MATB;
    constexpr uint32_t ST_AL = MATB;                      // only if ALO
    constexpr uint32_t ST_BH = (ALO ? 2 : 1) * MATB;
    constexpr uint32_t ST_BL = ST_BH + MATB;

    extern __shared__ char smem[];
    const uint32_t sbase = smem_u32(smem);

    const int tid  = threadIdx.x;
    const int lane = tid & 31;
    const int wid  = tid >> 5;
    const int m0 = blockIdx.y * BM;
    const int n0 = blockIdx.x * BN;

    const __half* AH = AHg + (size_t)blockIdx.z * sA;
    const __half* AL = ALO ? (ALg + (size_t)blockIdx.z * sA) : (const __half*)0;
    const __half* BH = BHg + (size_t)blockIdx.z * sB;
    const __half* BL = BLg + (size_t)blockIdx.z * sB;

    auto fill = [&](int stg, int kt) {
        const int kc = kt * BK;
        const uint32_t sb = sbase + stg * STG;
#pragma unroll
        for (int j = 0; j < 2; j++) {
            const int idx = tid + NTH * j;
            const int r  = idx >> 2;
            const int ch = idx & 3;
            const uint32_t so = (uint32_t)(r * ROWB + ch * 16);
            const size_t gao = (size_t)(m0 + r) * K + kc + ch * 8;
            const size_t gbo = (size_t)(n0 + r) * K + kc + ch * 8;
            cp16(sb + so, AH + gao);
            if (ALO) cp16(sb + ST_AL + so, AL + gao);
            cp16(sb + ST_BH + so, BH + gbo);
            cp16(sb + ST_BL + so, BL + gbo);
        }
        CP_COMMIT();
    };

    // warp tiling: 2 (M) x 4 (N) warps; warp tile 64x32
    const int warpM = wid & 1;
    const int warpN = wid >> 1;

    const int a_row = warpM * 64 + (lane & 15);
    const int a_kad = (lane >> 4) << 3;
    const int b_row = warpN * 32 + (lane & 7) + ((lane >> 4) << 3);
    const int b_kad = ((lane >> 3) & 1) << 3;

    float acc[4][4][4];
#pragma unroll
    for (int mi = 0; mi < 4; mi++)
#pragma unroll
        for (int ni = 0; ni < 4; ni++)
#pragma unroll
            for (int r = 0; r < 4; r++) acc[mi][ni][r] = 0.0f;

    const int KT = K / BK;

    fill(0, 0);
    fill(1, 1);

    for (int kt = 0; kt < KT; kt++) {
        // last iteration: its stage's cp.async group may be the newest one in
        // flight — CP_WAIT(1) would NOT guarantee it landed. Drain fully.
        if (kt == KT - 1) { CP_WAIT(0); } else { CP_WAIT(1); }
        __syncthreads();
        const uint32_t sb = sbase + (kt % NSTAGE) * STG;
        if (kt + NSTAGE - 1 < KT) fill((kt + NSTAGE - 1) % NSTAGE, kt + NSTAGE - 1);

#pragma unroll
        for (int ks = 0; ks < 2; ks++) {
            const int ko = ks * 16;
            uint32_t aH[4][4], aL[4][4];
#pragma unroll
            for (int mi = 0; mi < 4; mi++) {
                const uint32_t ad = sb
                    + (uint32_t)((a_row + mi * 16) * ROWB + (ko + a_kad) * 2);
                ldsm4(aH[mi], ad);
                if (ALO) ldsm4(aL[mi], ad + ST_AL);
            }
            uint32_t bHf[2][4], bLf[2][4];
#pragma unroll
            for (int nf = 0; nf < 2; nf++) {
                const uint32_t bd = sb + ST_BH
                    + (uint32_t)((b_row + nf * 16) * ROWB + (ko + b_kad) * 2);
                ldsm4(bHf[nf], bd);
                ldsm4(bLf[nf], bd + (ST_BL - ST_BH));
            }
#pragma unroll
            for (int mi = 0; mi < 4; mi++) {
#pragma unroll
                for (int ni = 0; ni < 4; ni++) {
                    const uint32_t* bh = &bHf[ni >> 1][(ni & 1) * 2];
                    const uint32_t* bl = &bLf[ni >> 1][(ni & 1) * 2];
                    mma16816(acc[mi][ni], aH[mi], bh[0], bh[1]);   // hi*hi
                    mma16816(acc[mi][ni], aH[mi], bl[0], bl[1]);   // hi*lo
                    if (ALO) mma16816(acc[mi][ni], aL[mi], bh[0], bh[1]); // lo*hi
                }
            }
        }
    }

    // ---------------------------- epilogue -------------------------------
    const int rq = lane >> 2;
    const int cq = (lane & 3) * 2;

    if (MODE == 2) {
        // stage hi/lo tiles transposed in smem, then coalesced global writes
        __syncthreads();   // pipeline smem no longer read; safe to reuse
        __half* bufh = (__half*)smem;
        __half* bufl = bufh + 128 * TSTR;
#pragma unroll
        for (int mi = 0; mi < 4; mi++) {
#pragma unroll
            for (int ni = 0; ni < 4; ni++) {
                const float* a4 = acc[mi][ni];
                const int lm = warpM * 64 + mi * 16 + rq;
                const int ln = warpN * 32 + ni * 8 + cq;
                const float b0 = bcoef * __ldg(&bias[n0 + ln]);
                const float b1 = bcoef * __ldg(&bias[n0 + ln + 1]);
#pragma unroll
                for (int h = 0; h < 2; h++) {
                    const int m = lm + h * 8;
                    const float v0 = alpha * a4[2 * h]     + b0;
                    const float v1 = alpha * a4[2 * h + 1] + b1;
                    const __half h0 = __float2half(v0);
                    const __half h1 = __float2half(v1);
                    bufh[ln * TSTR + m]       = h0;
                    bufh[(ln + 1) * TSTR + m] = h1;
                    bufl[ln * TSTR + m]       = __float2half(v0 - __half2float(h0));
                    bufl[(ln + 1) * TSTR + m] = __float2half(v1 - __half2float(h1));
                }
            }
        }
        __syncthreads();
        {
            const int ncol = tid & 127;
            const int sel  = tid >> 7;                     // 0 = hi, 1 = lo
            const __half* src = (sel ? bufl : bufh) + ncol * TSTR;
            const int bb  = m0 >> 12;
            const int m0s = m0 & 4095;
            __half* dst = (__half*)(sel ? O2 : O1)
                        + ((size_t)bb * HD + n0 + ncol) * SEQ + m0s;
#pragma unroll
            for (int q = 0; q < 16; q++)
                ((uint4*)dst)[q] = ((const uint4*)src)[q];
        }
        return;
    }

    const int mbase = m0 + warpM * 64;
    const int nbase = n0 + warpN * 32;
    const bool emit_lo = (O2 != (void*)0);

#pragma unroll
    for (int mi = 0; mi < 4; mi++) {
#pragma unroll
        for (int ni = 0; ni < 4; ni++) {
            const int mrow = mbase + mi * 16 + rq;
            const int ncol = nbase + ni * 8 + cq;
            const float* a4 = acc[mi][ni];

            if (MODE == 0) {
                float* o = (float*)O1 + (size_t)blockIdx.z * sO;
                *(float2*)(o + (size_t)mrow * N + ncol)       = make_float2(a4[0], a4[1]);
                *(float2*)(o + (size_t)(mrow + 8) * N + ncol) = make_float2(a4[2], a4[3]);
            } else {
                const float b0 = bcoef * __ldg(&bias[ncol]);
                const float b1 = bcoef * __ldg(&bias[ncol + 1]);
#pragma unroll
                for (int h = 0; h < 2; h++) {
                    const int m = mrow + h * 8;
                    const float v0 = alpha * a4[2 * h]     + b0;
                    const float v1 = alpha * a4[2 * h + 1] + b1;
                    const __half h0 = __float2half(v0);
                    const __half h1 = __float2half(v1);
                    __half* oh = (__half*)O1 + (size_t)m * N + ncol;
                    *(__half2*)oh = __halves2half2(h0, h1);
                    if (emit_lo) {
                        const __half l0 = __float2half(v0 - __half2float(h0));
                        const __half l1 = __float2half(v1 - __half2float(h1));
                        __half* ol = (__half*)O2 + (size_t)m * N + ncol;
                        *(__half2*)ol = __halves2half2(l0, l1);
                    }
                }
            }
        }
    }
}

// ============================================================================
// split kernels: hi = fp16(v); lo = fp16(v - hi)
// ============================================================================
// z=0: v = x;  z=1: v = x + rp
__global__ void split_x(const float* __restrict__ x, const float* __restrict__ rp,
                        __half* __restrict__ xsh, __half* __restrict__ xsl,
                        __half* __restrict__ xrh, __half* __restrict__ xrl)
{
    const int z = blockIdx.z;
    const int i = (blockIdx.x * blockDim.x + threadIdx.x) * 4;
    float4 v = *(const float4*)(x + i);
    if (z) {
        const float4 u = *(const float4*)(rp + i);
        v.x += u.x; v.y += u.y; v.z += u.z; v.w += u.w;
    }
    __half* hi = z ? xrh : xsh;
    __half* lo = z ? xrl : xsl;
    const __half h0 = __float2half(v.x), h1 = __float2half(v.y);
    const __half h2 = __float2half(v.z), h3 = __float2half(v.w);
    *(__half2*)(hi + i)     = __halves2half2(h0, h1);
    *(__half2*)(hi + i + 2) = __halves2half2(h2, h3);
    *(__half2*)(lo + i)     = __halves2half2(__float2half(v.x - __half2float(h0)),
                                             __float2half(v.y - __half2float(h1)));
    *(__half2*)(lo + i + 2) = __halves2half2(__float2half(v.z - __half2float(h2)),
                                             __float2half(v.w - __half2float(h3)));
}

// z selects one of 3 weight matrices
__global__ void split_w(const float* __restrict__ w0, const float* __restrict__ w1,
                        const float* __restrict__ w2,
                        __half* __restrict__ h0p, __half* __restrict__ l0p,
                        __half* __restrict__ h1p, __half* __restrict__ l1p,
                        __half* __restrict__ h2p, __half* __restrict__ l2p)
{
    const int z = blockIdx.z;
    const float* a = (z == 0) ? w0 : (z == 1) ? w1 : w2;
    __half* hi = (z == 0) ? h0p : (z == 1) ? h1p : h2p;
    __half* lo = (z == 0) ? l0p : (z == 1) ? l1p : l2p;
    const int i = (blockIdx.x * blockDim.x + threadIdx.x) * 4;
    const float4 v = *(const float4*)(a + i);
    const __half h0 = __float2half(v.x), h1 = __float2half(v.y);
    const __half h2 = __float2half(v.z), h3 = __float2half(v.w);
    *(__half2*)(hi + i)     = __halves2half2(h0, h1);
    *(__half2*)(hi + i + 2) = __halves2half2(h2, h3);
    *(__half2*)(lo + i)     = __halves2half2(__float2half(v.x - __half2float(h0)),
                                             __float2half(v.y - __half2float(h1)));
    *(__half2*)(lo + i + 2) = __halves2half2(__float2half(v.z - __half2float(h2)),
                                             __float2half(v.w - __half2float(h3)));
}

// ============================================================================
// Row softmax over n=4096, emits P as fp16 (hi only). Pointers pre-offset.
// ============================================================================
__global__ void softmax_rows(const float* __restrict__ S, __half* __restrict__ ph)
{
    const int n = 4096;
    const size_t base = (size_t)blockIdx.x * n;
    const float* p = S + base;
    const int t = threadIdx.x;

    float4 v[4];
#pragma unroll
    for (int i = 0; i < 4; i++) v[i] = *(const float4*)(p + (size_t)(i * 256 + t) * 4);

    __shared__ float redm[8];
    __shared__ float reds[8];

    float mx = -3.4e38f;
#pragma unroll
    for (int i = 0; i < 4; i++)
        mx = fmaxf(mx, fmaxf(fmaxf(v[i].x, v[i].y), fmaxf(v[i].z, v[i].w)));
#pragma unroll
    for (int o = 16; o; o >>= 1) mx = fmaxf(mx, __shfl_xor_sync(0xffffffffu, mx, o));
    if ((t & 31) == 0) redm[t >> 5] = mx;
    __syncthreads();
    float m = redm[0];
#pragma unroll
    for (int i = 1; i < 8; i++) m = fmaxf(m, redm[i]);

    float sum = 0.0f;
#pragma unroll
    for (int i = 0; i < 4; i++) {
        v[i].x = __expf(v[i].x - m);
        v[i].y = __expf(v[i].y - m);
        v[i].z = __expf(v[i].z - m);
        v[i].w = __expf(v[i].w - m);
        sum += (v[i].x + v[i].y) + (v[i].z + v[i].w);
    }
#pragma unroll
    for (int o = 16; o; o >>= 1) sum += __shfl_xor_sync(0xffffffffu, sum, o);
    if ((t & 31) == 0) reds[t >> 5] = sum;
    __syncthreads();
    float stot = 0.0f;
#pragma unroll
    for (int i = 0; i < 8; i++) stot += reds[i];
    const float inv = 1.0f / stot;

#pragma unroll
    for (int i = 0; i < 4; i++) {
        const int idx = (i * 256 + t) * 4;
        *(__half2*)(ph + base + idx)     = __halves2half2(__float2half(v[i].x * inv),
                                                          __float2half(v[i].y * inv));
        *(__half2*)(ph + base + idx + 2) = __halves2half2(__float2half(v[i].z * inv),
                                                          __float2half(v[i].w * inv));
    }
}

// ============================================================================
// kernel_launch
// ============================================================================
extern "C" void kernel_launch(void* const* d_in, const int* in_sizes, int n_in,
                              void* d_out, int out_size)
{
    (void)in_sizes; (void)n_in; (void)out_size;
    const float* x  = (const float*)d_in[0];
    const float* rp = (const float*)d_in[1];
    const float* Wq = (const float*)d_in[2];
    const float* bq = (const float*)d_in[3];
    const float* Wk = (const float*)d_in[4];
    const float* bk = (const float*)d_in[5];
    const float* Wv = (const float*)d_in[6];
    const float* bv = (const float*)d_in[7];
    float* out = (float*)d_out;

    __half *xsh, *xsl, *xrh, *xrl, *wqh, *wql, *wkh, *wkl, *wvh, *wvl;
    __half *qh, *kh, *kl, *vth, *vtl, *ph;
    float* S;
    cudaGetSymbolAddress((void**)&xsh, g_xsh); cudaGetSymbolAddress((void**)&xsl, g_xsl);
    cudaGetSymbolAddress((void**)&xrh, g_xrh); cudaGetSymbolAddress((void**)&xrl, g_xrl);
    cudaGetSymbolAddress((void**)&wqh, g_wqh); cudaGetSymbolAddress((void**)&wql, g_wql);
    cudaGetSymbolAddress((void**)&wkh, g_wkh); cudaGetSymbolAddress((void**)&wkl, g_wkl);
    cudaGetSymbolAddress((void**)&wvh, g_wvh); cudaGetSymbolAddress((void**)&wvl, g_wvl);
    cudaGetSymbolAddress((void**)&qh,  g_qh);
    cudaGetSymbolAddress((void**)&kh,  g_kh);  cudaGetSymbolAddress((void**)&kl,  g_kl);
    cudaGetSymbolAddress((void**)&vth, g_vth); cudaGetSymbolAddress((void**)&vtl, g_vtl);
    cudaGetSymbolAddress((void**)&ph,  g_ph);
    cudaGetSymbolAddress((void**)&S,   g_S);

    cudaFuncSetAttribute((const void*)mma_nt<1, false, 2>,
                         cudaFuncAttributeMaxDynamicSharedMemorySize, SMEM_NOA);
    cudaFuncSetAttribute((const void*)mma_nt<1, true, 1>,
                         cudaFuncAttributeMaxDynamicSharedMemorySize, SMEM_ALO);
    cudaFuncSetAttribute((const void*)mma_nt<2, true, 1>,
                         cudaFuncAttributeMaxDynamicSharedMemorySize, SMEM_ALO);
    cudaFuncSetAttribute((const void*)mma_nt<0, false, 2>,
                         cudaFuncAttributeMaxDynamicSharedMemorySize, SMEM_NOA);

    const float sc = (float)(1.0 / sqrt((double)HD));

    // --- splits (2 launches) ---
    split_x<<<dim3(TOK * HD / 1024, 1, 2), 256>>>(x, rp, xsh, xsl, xrh, xrl);
    split_w<<<dim3(HD * HD / 1024, 1, 3), 256>>>(Wq, Wk, Wv,
                                                 wqh, wql, wkh, wkl, wvh, wvl);

    // --- projections (W is [out,in] row-major = [N,K]) ---
    // Q: asymmetric 2-MMA (Q is consumed fp16-truncated downstream anyway).
    mma_nt<1, false, 2><<<dim3(HD / BN, TOK / BM, 1), NTH, SMEM_NOA>>>(
        xsh, (const __half*)0, wqh, wql, bq, sc, sc, qh, (void*)0, HD, HD, 0, 0, 0);
    // K': full 3-MMA split (its lo output must be accurate).
    mma_nt<1, true, 1><<<dim3(HD / BN, TOK / BM, 1), NTH, SMEM_ALO>>>(
        xrh, xrl, wkh, wkl, bk, 1.0f, 2.0f, kh, kl, HD, HD, 0, 0, 0);
    // V: full 3-MMA split, transposed coalesced epilogue.
    mma_nt<2, true, 1><<<dim3(HD / BN, TOK / BM, 1), NTH, SMEM_ALO>>>(
        xsh, xsl, wvh, wvl, bv, 1.0f, 1.0f, vth, vtl, HD, HD, 0, 0, 0);

    // --- per-batch QK -> softmax so S (64 MB/batch) stays L2-resident ---
    for (int b = 0; b < NB; b++) {
        const __half* qb = qh + (size_t)b * SEQ * HD;
        const __half* kb = kh + (size_t)b * SEQ * HD;
        const __half* lb = kl + (size_t)b * SEQ * HD;
        float* Sb = S + (size_t)b * SEQ * SEQ;
        mma_nt<0, false, 2><<<dim3(SEQ / BN, SEQ / BM, 1), NTH, SMEM_NOA>>>(
            qb, (const __half*)0, kb, lb, (const float*)0, 1.0f, 0.0f,
            Sb, (void*)0, SEQ, HD, 0, 0, 0);
        softmax_rows<<<SEQ, 256>>>(Sb, ph + (size_t)b * SEQ * SEQ);
    }

    // --- out: O[b] = Ph[b] · Vt(hi,lo)[b]^T (2-MMA asymmetric, fp32 out) ---
    mma_nt<0, false, 2><<<dim3(HD / BN, SEQ / BM, NB), NTH, SMEM_NOA>>>(
        ph, (const __half*)0, vth, vtl, (const float*)0, 1.0f, 0.0f, out, (void*)0,
        HD, SEQ, (size_t)SEQ * SEQ, (size_t)HD * SEQ, (size_t)SEQ * HD);
}

// round 9
// speedup vs baseline: 3.5907x; 1.1044x over previous
#include <cuda_runtime.h>
#include <cuda_fp16.h>
#include <math.h>
#include <stdint.h>

// ============================================================================
// ResponseAttention via mma.sync (m16n8k16 fp16), asymmetric Ozaki split.
//   scores = Qs · K'^T, Qs=(x·Wq^T+bq)/sqrt(H), K'=(x+rp)·Wk^T+2bk
//   out    = softmax(scores) · V   (V stored transposed so P·V is NT too)
// ALL GEMMs use the asymmetric 2-MMA split: A fp16-hi only, B = (hi, lo):
//   A_hi·B_hi + A_hi·B_lo, fp32 accumulate.  rel_err ~5e-4 < 1e-3 gate.
// Every kernel fits 2 CTAs/SM (<=128 regs, 92KB smem) -> 16 warps/SM.
// R9: all-2-MMA (regs were blocking 2 CTA/SM on 3-MMA kernels, ncu showed
// tensor=42%/occ=12.4% on K' proj), fused single-launch projections.
// tcgen05 unavailable (compute_103 virtual arch) — mma.sync is the path.
// B=4, S=4096, H=512.
// ============================================================================

#define BM 128
#define BN 128
#define BK 32
#define NSTAGE 3
#define NTH 256

#define TOK 16384
#define HD  512
#define SEQ 4096
#define NB  4

// smem: rows of 32 fp16 padded to 40 (80 B) -> conflict-free ldmatrix
#define ROWB 80
#define MATB (128 * ROWB)                       // one 128x32 fp16 matrix: 10240 B
#define ST_BH MATB
#define ST_BL (2 * MATB)
#define STG   (3 * MATB)                        // AH BH BL
#define SMEM_BYTES (NSTAGE * STG)               // 92160

#define TSTR 136                                // transpose-buffer row stride (halves)

// ---------------------------- scratch ------------------------------------
__device__ __half g_xsh[TOK * HD];
__device__ __half g_xrh[TOK * HD];
__device__ __half g_wqh[HD * HD], g_wql[HD * HD];
__device__ __half g_wkh[HD * HD], g_wkl[HD * HD];
__device__ __half g_wvh[HD * HD], g_wvl[HD * HD];
__device__ __half g_qh[TOK * HD];
__device__ __half g_kh[TOK * HD], g_kl[TOK * HD];
__device__ __half g_vth[TOK * HD], g_vtl[TOK * HD];
__device__ float  g_S[(size_t)NB * SEQ * SEQ];
__device__ __half g_ph[(size_t)NB * SEQ * SEQ];

// ---------------------------- helpers ------------------------------------
__device__ __forceinline__ uint32_t smem_u32(const void* p) {
    uint32_t a;
    asm("{ .reg .u64 t; cvta.to.shared.u64 t, %1; cvt.u32.u64 %0, t; }"
        : "=r"(a) : "l"(p));
    return a;
}
__device__ __forceinline__ void cp16(uint32_t s, const void* g) {
    asm volatile("cp.async.cg.shared.global [%0], [%1], 16;" :: "r"(s), "l"(g));
}
#define CP_COMMIT() asm volatile("cp.async.commit_group;")
#define CP_WAIT(n)  asm volatile("cp.async.wait_group %0;" :: "n"(n))

__device__ __forceinline__ void ldsm4(uint32_t r[4], uint32_t addr) {
    asm volatile("ldmatrix.sync.aligned.m8n8.x4.shared.b16 {%0,%1,%2,%3}, [%4];"
        : "=r"(r[0]), "=r"(r[1]), "=r"(r[2]), "=r"(r[3]) : "r"(addr));
}
__device__ __forceinline__ void mma16816(float acc[4], const uint32_t a[4],
                                         const uint32_t b0, const uint32_t b1) {
    asm volatile(
        "mma.sync.aligned.m16n8k16.row.col.f32.f16.f16.f32 "
        "{%0,%1,%2,%3}, {%4,%5,%6,%7}, {%8,%9}, {%0,%1,%2,%3};"
        : "+f"(acc[0]), "+f"(acc[1]), "+f"(acc[2]), "+f"(acc[3])
        : "r"(a[0]), "r"(a[1]), "r"(a[2]), "r"(a[3]), "r"(b0), "r"(b1));
}

// ---------------------------------------------------------------------------
// Shared mainloop: C[128,128] tile of A_hi[M,K] * (B_hi+B_lo)[N,K]^T.
// 2 MMAs per fragment (hi*hi + hi*lo). acc[4][4][4], 8 warps (2M x 4N).
// ---------------------------------------------------------------------------
struct TileCtx {
    uint32_t sbase;
    int tid, lane, wid, warpM, warpN;
    int a_row, a_kad, b_row, b_kad;
};

__device__ __forceinline__ void mainloop_2mma(
    const TileCtx& c, const __half* AH, const __half* BH, const __half* BL,
    int m0, int n0, int K, float acc[4][4][4])
{
#pragma unroll
    for (int mi = 0; mi < 4; mi++)
#pragma unroll
        for (int ni = 0; ni < 4; ni++)
#pragma unroll
            for (int r = 0; r < 4; r++) acc[mi][ni][r] = 0.0f;

    auto fill = [&](int stg, int kt) {
        const int kc = kt * BK;
        const uint32_t sb = c.sbase + stg * STG;
#pragma unroll
        for (int j = 0; j < 2; j++) {
            const int idx = c.tid + NTH * j;
            const int r  = idx >> 2;
            const int ch = idx & 3;
            const uint32_t so = (uint32_t)(r * ROWB + ch * 16);
            cp16(sb + so,        AH + (size_t)(m0 + r) * K + kc + ch * 8);
            cp16(sb + ST_BH + so, BH + (size_t)(n0 + r) * K + kc + ch * 8);
            cp16(sb + ST_BL + so, BL + (size_t)(n0 + r) * K + kc + ch * 8);
        }
        CP_COMMIT();
    };

    const int KT = K / BK;
    fill(0, 0);
    fill(1, 1);

    for (int kt = 0; kt < KT; kt++) {
        if (kt == KT - 1) { CP_WAIT(0); } else { CP_WAIT(1); }
        __syncthreads();
        const uint32_t sb = c.sbase + (kt % NSTAGE) * STG;
        if (kt + NSTAGE - 1 < KT) fill((kt + NSTAGE - 1) % NSTAGE, kt + NSTAGE - 1);

#pragma unroll
        for (int ks = 0; ks < 2; ks++) {
            const int ko = ks * 16;
            uint32_t aH[4][4];
#pragma unroll
            for (int mi = 0; mi < 4; mi++) {
                const uint32_t ad = sb
                    + (uint32_t)((c.a_row + mi * 16) * ROWB + (ko + c.a_kad) * 2);
                ldsm4(aH[mi], ad);
            }
            uint32_t bHf[2][4], bLf[2][4];
#pragma unroll
            for (int nf = 0; nf < 2; nf++) {
                const uint32_t bd = sb + ST_BH
                    + (uint32_t)((c.b_row + nf * 16) * ROWB + (ko + c.b_kad) * 2);
                ldsm4(bHf[nf], bd);
                ldsm4(bLf[nf], bd + (ST_BL - ST_BH));
            }
#pragma unroll
            for (int mi = 0; mi < 4; mi++) {
#pragma unroll
                for (int ni = 0; ni < 4; ni++) {
                    const uint32_t* bh = &bHf[ni >> 1][(ni & 1) * 2];
                    const uint32_t* bl = &bLf[ni >> 1][(ni & 1) * 2];
                    mma16816(acc[mi][ni], aH[mi], bh[0], bh[1]);
                    mma16816(acc[mi][ni], aH[mi], bl[0], bl[1]);
                }
            }
        }
    }
}

__device__ __forceinline__ TileCtx make_ctx(uint32_t sbase) {
    TileCtx c;
    c.sbase = sbase;
    c.tid  = threadIdx.x;
    c.lane = c.tid & 31;
    c.wid  = c.tid >> 5;
    c.warpM = c.wid & 1;
    c.warpN = c.wid >> 1;
    c.a_row = c.warpM * 64 + (c.lane & 15);
    c.a_kad = (c.lane >> 4) << 3;
    c.b_row = c.warpN * 32 + (c.lane & 7) + ((c.lane >> 4) << 3);
    c.b_kad = ((c.lane >> 3) & 1) << 3;
    return c;
}

// ============================================================================
// Fused projections: one launch, grid (12, 128).
//   z = blockIdx.x>>2:  0 -> Q (hi out),  1 -> K' (hi+lo out),
//                       2 -> V (hi+lo out, transposed per batch)
// ============================================================================
__global__ __launch_bounds__(NTH, 2)
void proj3(const __half* __restrict__ xsh, const __half* __restrict__ xrh,
           const __half* __restrict__ wqh, const __half* __restrict__ wql,
           const __half* __restrict__ wkh, const __half* __restrict__ wkl,
           const __half* __restrict__ wvh, const __half* __restrict__ wvl,
           const float* __restrict__ bq, const float* __restrict__ bk,
           const float* __restrict__ bv, float sc,
           __half* __restrict__ qh,
           __half* __restrict__ kh, __half* __restrict__ kl,
           __half* __restrict__ vth, __half* __restrict__ vtl)
{
    extern __shared__ char smem[];
    TileCtx c = make_ctx(smem_u32(smem));

    const int z  = blockIdx.x >> 2;
    const int n0 = (blockIdx.x & 3) * BN;
    const int m0 = blockIdx.y * BM;

    const __half* AH = (z == 1) ? xrh : xsh;
    const __half* BH = (z == 0) ? wqh : (z == 1) ? wkh : wvh;
    const __half* BL = (z == 0) ? wql : (z == 1) ? wkl : wvl;
    const float* bias = (z == 0) ? bq : (z == 1) ? bk : bv;
    const float alpha = (z == 0) ? sc : 1.0f;
    const float bcoef = (z == 0) ? sc : (z == 1) ? 2.0f : 1.0f;

    float acc[4][4][4];
    mainloop_2mma(c, AH, BH, BL, m0, n0, HD, acc);

    const int rq = c.lane >> 2;
    const int cq = (c.lane & 3) * 2;

    if (z == 2) {
        // stage hi/lo tiles transposed in smem, then coalesced global writes
        __syncthreads();
        __half* bufh = (__half*)smem;
        __half* bufl = bufh + 128 * TSTR;
#pragma unroll
        for (int mi = 0; mi < 4; mi++) {
#pragma unroll
            for (int ni = 0; ni < 4; ni++) {
                const float* a4 = acc[mi][ni];
                const int lm = c.warpM * 64 + mi * 16 + rq;
                const int ln = c.warpN * 32 + ni * 8 + cq;
                const float b0 = bcoef * __ldg(&bias[n0 + ln]);
                const float b1 = bcoef * __ldg(&bias[n0 + ln + 1]);
#pragma unroll
                for (int h = 0; h < 2; h++) {
                    const int m = lm + h * 8;
                    const float v0 = alpha * a4[2 * h]     + b0;
                    const float v1 = alpha * a4[2 * h + 1] + b1;
                    const __half h0 = __float2half(v0);
                    const __half h1 = __float2half(v1);
                    bufh[ln * TSTR + m]       = h0;
                    bufh[(ln + 1) * TSTR + m] = h1;
                    bufl[ln * TSTR + m]       = __float2half(v0 - __half2float(h0));
                    bufl[(ln + 1) * TSTR + m] = __float2half(v1 - __half2float(h1));
                }
            }
        }
        __syncthreads();
        const int ncol = c.tid & 127;
        const int sel  = c.tid >> 7;                     // 0 = hi, 1 = lo
        const __half* src = (sel ? bufl : bufh) + ncol * TSTR;
        const int bb  = m0 >> 12;
        const int m0s = m0 & 4095;
        __half* dst = (sel ? vtl : vth)
                    + ((size_t)bb * HD + n0 + ncol) * SEQ + m0s;
#pragma unroll
        for (int q = 0; q < 16; q++)
            ((uint4*)dst)[q] = ((const uint4*)src)[q];
        return;
    }

    const bool emit_lo = (z == 1);
    __half* O1 = (z == 0) ? qh : kh;
#pragma unroll
    for (int mi = 0; mi < 4; mi++) {
#pragma unroll
        for (int ni = 0; ni < 4; ni++) {
            const int mrow = m0 + c.warpM * 64 + mi * 16 + rq;
            const int ncol = n0 + c.warpN * 32 + ni * 8 + cq;
            const float* a4 = acc[mi][ni];
            const float b0 = bcoef * __ldg(&bias[ncol]);
            const float b1 = bcoef * __ldg(&bias[ncol + 1]);
#pragma unroll
            for (int h = 0; h < 2; h++) {
                const int m = mrow + h * 8;
                const float v0 = alpha * a4[2 * h]     + b0;
                const float v1 = alpha * a4[2 * h + 1] + b1;
                const __half h0 = __float2half(v0);
                const __half h1 = __float2half(v1);
                *(__half2*)(O1 + (size_t)m * HD + ncol) = __halves2half2(h0, h1);
                if (emit_lo) {
                    const __half l0 = __float2half(v0 - __half2float(h0));
                    const __half l1 = __float2half(v1 - __half2float(h1));
                    *(__half2*)(kl + (size_t)m * HD + ncol) = __halves2half2(l0, l1);
                }
            }
        }
    }
}

// ============================================================================
// Big GEMM: fp32 out, C[M,N] = A_hi[M,K] * (B_hi+B_lo)[N,K]^T  (QK, PV)
// ============================================================================
__global__ __launch_bounds__(NTH, 2)
void mma_big(const __half* __restrict__ AHg,
             const __half* __restrict__ BHg, const __half* __restrict__ BLg,
             float* __restrict__ Og,
             int N, int K, size_t sA, size_t sB, size_t sO)
{
    extern __shared__ char smem[];
    TileCtx c = make_ctx(smem_u32(smem));

    const int m0 = blockIdx.y * BM;
    const int n0 = blockIdx.x * BN;
    const __half* AH = AHg + (size_t)blockIdx.z * sA;
    const __half* BH = BHg + (size_t)blockIdx.z * sB;
    const __half* BL = BLg + (size_t)blockIdx.z * sB;
    float* O = Og + (size_t)blockIdx.z * sO;

    float acc[4][4][4];
    mainloop_2mma(c, AH, BH, BL, m0, n0, K, acc);

    const int rq = c.lane >> 2;
    const int cq = (c.lane & 3) * 2;
#pragma unroll
    for (int mi = 0; mi < 4; mi++) {
#pragma unroll
        for (int ni = 0; ni < 4; ni++) {
            const int mrow = m0 + c.warpM * 64 + mi * 16 + rq;
            const int ncol = n0 + c.warpN * 32 + ni * 8 + cq;
            const float* a4 = acc[mi][ni];
            *(float2*)(O + (size_t)mrow * N + ncol)       = make_float2(a4[0], a4[1]);
            *(float2*)(O + (size_t)(mrow + 8) * N + ncol) = make_float2(a4[2], a4[3]);
        }
    }
}

// ============================================================================
// split kernels
// ============================================================================
// hi-only split of x (z=0) and x+rp (z=1)
__global__ void split_x(const float* __restrict__ x, const float* __restrict__ rp,
                        __half* __restrict__ xsh, __half* __restrict__ xrh)
{
    const int z = blockIdx.z;
    const int i = (blockIdx.x * blockDim.x + threadIdx.x) * 4;
    float4 v = *(const float4*)(x + i);
    if (z) {
        const float4 u = *(const float4*)(rp + i);
        v.x += u.x; v.y += u.y; v.z += u.z; v.w += u.w;
    }
    __half* hi = z ? xrh : xsh;
    *(__half2*)(hi + i)     = __halves2half2(__float2half(v.x), __float2half(v.y));
    *(__half2*)(hi + i + 2) = __halves2half2(__float2half(v.z), __float2half(v.w));
}

// hi+lo split of the 3 weight matrices (z selects)
__global__ void split_w(const float* __restrict__ w0, const float* __restrict__ w1,
                        const float* __restrict__ w2,
                        __half* __restrict__ h0p, __half* __restrict__ l0p,
                        __half* __restrict__ h1p, __half* __restrict__ l1p,
                        __half* __restrict__ h2p, __half* __restrict__ l2p)
{
    const int z = blockIdx.z;
    const float* a = (z == 0) ? w0 : (z == 1) ? w1 : w2;
    __half* hi = (z == 0) ? h0p : (z == 1) ? h1p : h2p;
    __half* lo = (z == 0) ? l0p : (z == 1) ? l1p : l2p;
    const int i = (blockIdx.x * blockDim.x + threadIdx.x) * 4;
    const float4 v = *(const float4*)(a + i);
    const __half h0 = __float2half(v.x), h1 = __float2half(v.y);
    const __half h2 = __float2half(v.z), h3 = __float2half(v.w);
    *(__half2*)(hi + i)     = __halves2half2(h0, h1);
    *(__half2*)(hi + i + 2) = __halves2half2(h2, h3);
    *(__half2*)(lo + i)     = __halves2half2(__float2half(v.x - __half2float(h0)),
                                             __float2half(v.y - __half2float(h1)));
    *(__half2*)(lo + i + 2) = __halves2half2(__float2half(v.z - __half2float(h2)),
                                             __float2half(v.w - __half2float(h3)));
}

// ============================================================================
// Row softmax over n=4096, emits P as fp16 (hi only).
// ============================================================================
__global__ void softmax_rows(const float* __restrict__ S, __half* __restrict__ ph)
{
    const int n = 4096;
    const size_t base = (size_t)blockIdx.x * n;
    const float* p = S + base;
    const int t = threadIdx.x;

    float4 v[4];
#pragma unroll
    for (int i = 0; i < 4; i++) v[i] = *(const float4*)(p + (size_t)(i * 256 + t) * 4);

    __shared__ float redm[8];
    __shared__ float reds[8];

    float mx = -3.4e38f;
#pragma unroll
    for (int i = 0; i < 4; i++)
        mx = fmaxf(mx, fmaxf(fmaxf(v[i].x, v[i].y), fmaxf(v[i].z, v[i].w)));
#pragma unroll
    for (int o = 16; o; o >>= 1) mx = fmaxf(mx, __shfl_xor_sync(0xffffffffu, mx, o));
    if ((t & 31) == 0) redm[t >> 5] = mx;
    __syncthreads();
    float m = redm[0];
#pragma unroll
    for (int i = 1; i < 8; i++) m = fmaxf(m, redm[i]);

    float sum = 0.0f;
#pragma unroll
    for (int i = 0; i < 4; i++) {
        v[i].x = __expf(v[i].x - m);
        v[i].y = __expf(v[i].y - m);
        v[i].z = __expf(v[i].z - m);
        v[i].w = __expf(v[i].w - m);
        sum += (v[i].x + v[i].y) + (v[i].z + v[i].w);
    }
#pragma unroll
    for (int o = 16; o; o >>= 1) sum += __shfl_xor_sync(0xffffffffu, sum, o);
    if ((t & 31) == 0) reds[t >> 5] = sum;
    __syncthreads();
    float stot = 0.0f;
#pragma unroll
    for (int i = 0; i < 8; i++) stot += reds[i];
    const float inv = 1.0f / stot;

#pragma unroll
    for (int i = 0; i < 4; i++) {
        const int idx = (i * 256 + t) * 4;
        *(__half2*)(ph + base + idx)     = __halves2half2(__float2half(v[i].x * inv),
                                                          __float2half(v[i].y * inv));
        *(__half2*)(ph + base + idx + 2) = __halves2half2(__float2half(v[i].z * inv),
                                                          __float2half(v[i].w * inv));
    }
}

// ============================================================================
// kernel_launch
// ============================================================================
extern "C" void kernel_launch(void* const* d_in, const int* in_sizes, int n_in,
                              void* d_out, int out_size)
{
    (void)in_sizes; (void)n_in; (void)out_size;
    const float* x  = (const float*)d_in[0];
    const float* rp = (const float*)d_in[1];
    const float* Wq = (const float*)d_in[2];
    const float* bq = (const float*)d_in[3];
    const float* Wk = (const float*)d_in[4];
    const float* bk = (const float*)d_in[5];
    const float* Wv = (const float*)d_in[6];
    const float* bv = (const float*)d_in[7];
    float* out = (float*)d_out;

    __half *xsh, *xrh, *wqh, *wql, *wkh, *wkl, *wvh, *wvl;
    __half *qh, *kh, *kl, *vth, *vtl, *ph;
    float* S;
    cudaGetSymbolAddress((void**)&xsh, g_xsh);
    cudaGetSymbolAddress((void**)&xrh, g_xrh);
    cudaGetSymbolAddress((void**)&wqh, g_wqh); cudaGetSymbolAddress((void**)&wql, g_wql);
    cudaGetSymbolAddress((void**)&wkh, g_wkh); cudaGetSymbolAddress((void**)&wkl, g_wkl);
    cudaGetSymbolAddress((void**)&wvh, g_wvh); cudaGetSymbolAddress((void**)&wvl, g_wvl);
    cudaGetSymbolAddress((void**)&qh,  g_qh);
    cudaGetSymbolAddress((void**)&kh,  g_kh);  cudaGetSymbolAddress((void**)&kl,  g_kl);
    cudaGetSymbolAddress((void**)&vth, g_vth); cudaGetSymbolAddress((void**)&vtl, g_vtl);
    cudaGetSymbolAddress((void**)&ph,  g_ph);
    cudaGetSymbolAddress((void**)&S,   g_S);

    cudaFuncSetAttribute((const void*)proj3,
                         cudaFuncAttributeMaxDynamicSharedMemorySize, SMEM_BYTES);
    cudaFuncSetAttribute((const void*)mma_big,
                         cudaFuncAttributeMaxDynamicSharedMemorySize, SMEM_BYTES);

    const float sc = (float)(1.0 / sqrt((double)HD));

    // --- splits (2 launches) ---
    split_x<<<dim3(TOK * HD / 1024, 1, 2), 256>>>(x, rp, xsh, xrh);
    split_w<<<dim3(HD * HD / 1024, 1, 3), 256>>>(Wq, Wk, Wv,
                                                 wqh, wql, wkh, wkl, wvh, wvl);

    // --- fused projections: Q | K' | V(transposed), one launch ---
    proj3<<<dim3(12, TOK / BM), NTH, SMEM_BYTES>>>(
        xsh, xrh, wqh, wql, wkh, wkl, wvh, wvl,
        bq, bk, bv, sc, qh, kh, kl, vth, vtl);

    // --- per-batch QK -> softmax so S (64 MB/batch) stays L2-resident ---
    for (int b = 0; b < NB; b++) {
        const __half* qb = qh + (size_t)b * SEQ * HD;
        const __half* kb = kh + (size_t)b * SEQ * HD;
        const __half* lb = kl + (size_t)b * SEQ * HD;
        float* Sb = S + (size_t)b * SEQ * SEQ;
        mma_big<<<dim3(SEQ / BN, SEQ / BM, 1), NTH, SMEM_BYTES>>>(
            qb, kb, lb, Sb, SEQ, HD, 0, 0, 0);
        softmax_rows<<<SEQ, 256>>>(Sb, ph + (size_t)b * SEQ * SEQ);
    }

    // --- out: O[b] = Ph[b] · Vt(hi,lo)[b]^T ---
    mma_big<<<dim3(HD / BN, SEQ / BM, NB), NTH, SMEM_BYTES>>>(
        ph, vth, vtl, out,
        HD, SEQ, (size_t)SEQ * SEQ, (size_t)HD * SEQ, (size_t)SEQ * HD);
}

// round 10
// speedup vs baseline: 4.3898x; 1.2225x over previous
#include <cuda_runtime.h>
#include <cuda_fp16.h>
#include <math.h>
#include <stdint.h>

// ============================================================================
// ResponseAttention via mma.sync (m16n8k16 fp16), asymmetric Ozaki split.
//   scores = Qs · K'^T, Qs=(x·Wq^T+bq)/sqrt(H), K'=(x+rp)·Wk^T+2bk
//   out    = softmax(scores) · V   (V stored transposed so P·V is NT too)
// Projections + QK: 2-MMA asymmetric split (A hi-only, B hi+lo).
// PV: 1-MMA plain fp16 (P hi, V hi) — V truncation adds ~2.8e-4 in
// quadrature, total ~5.5e-4 < 1e-3 gate.
// R10: PV 1-MMA; single batched QK launch (tail amortization); single
// softmax launch; V projection emits hi only.
// tcgen05 unavailable (compute_103 virtual arch) — mma.sync is the path.
// B=4, S=4096, H=512.
// ============================================================================

#define BM 128
#define BN 128
#define BK 32
#define NSTAGE 3
#define NTH 256

#define TOK 16384
#define HD  512
#define SEQ 4096
#define NB  4

// smem: rows of 32 fp16 padded to 40 (80 B) -> conflict-free ldmatrix
#define ROWB 80
#define MATB (128 * ROWB)                       // one 128x32 fp16 matrix: 10240 B
#define SMEM_B3 (NSTAGE * 3 * MATB)             // 92160 (A BH BL)
#define SMEM_B2 (NSTAGE * 2 * MATB)             // 61440 (A BH)

#define TSTR 136                                // transpose-buffer row stride (halves)

// ---------------------------- scratch ------------------------------------
__device__ __half g_xsh[TOK * HD];
__device__ __half g_xrh[TOK * HD];
__device__ __half g_wqh[HD * HD], g_wql[HD * HD];
__device__ __half g_wkh[HD * HD], g_wkl[HD * HD];
__device__ __half g_wvh[HD * HD], g_wvl[HD * HD];
__device__ __half g_qh[TOK * HD];
__device__ __half g_kh[TOK * HD], g_kl[TOK * HD];
__device__ __half g_vth[TOK * HD];
__device__ float  g_S[(size_t)NB * SEQ * SEQ];
__device__ __half g_ph[(size_t)NB * SEQ * SEQ];

// ---------------------------- helpers ------------------------------------
__device__ __forceinline__ uint32_t smem_u32(const void* p) {
    uint32_t a;
    asm("{ .reg .u64 t; cvta.to.shared.u64 t, %1; cvt.u32.u64 %0, t; }"
        : "=r"(a) : "l"(p));
    return a;
}
__device__ __forceinline__ void cp16(uint32_t s, const void* g) {
    asm volatile("cp.async.cg.shared.global [%0], [%1], 16;" :: "r"(s), "l"(g));
}
#define CP_COMMIT() asm volatile("cp.async.commit_group;")
#define CP_WAIT(n)  asm volatile("cp.async.wait_group %0;" :: "n"(n))

__device__ __forceinline__ void ldsm4(uint32_t r[4], uint32_t addr) {
    asm volatile("ldmatrix.sync.aligned.m8n8.x4.shared.b16 {%0,%1,%2,%3}, [%4];"
        : "=r"(r[0]), "=r"(r[1]), "=r"(r[2]), "=r"(r[3]) : "r"(addr));
}
__device__ __forceinline__ void mma16816(float acc[4], const uint32_t a[4],
                                         const uint32_t b0, const uint32_t b1) {
    asm volatile(
        "mma.sync.aligned.m16n8k16.row.col.f32.f16.f16.f32 "
        "{%0,%1,%2,%3}, {%4,%5,%6,%7}, {%8,%9}, {%0,%1,%2,%3};"
        : "+f"(acc[0]), "+f"(acc[1]), "+f"(acc[2]), "+f"(acc[3])
        : "r"(a[0]), "r"(a[1]), "r"(a[2]), "r"(a[3]), "r"(b0), "r"(b1));
}

// ---------------------------------------------------------------------------
// Shared mainloop: C[128,128] tile of A_hi[M,K] * B[N,K]^T.
//   BLO=true : B = (hi, lo), 2 MMAs per fragment
//   BLO=false: B = hi only,  1 MMA per fragment
// acc[4][4][4], 8 warps (2M x 4N), 3-stage cp.async pipeline.
// ---------------------------------------------------------------------------
struct TileCtx {
    uint32_t sbase;
    int tid, lane, wid, warpM, warpN;
    int a_row, a_kad, b_row, b_kad;
};

__device__ __forceinline__ TileCtx make_ctx(uint32_t sbase) {
    TileCtx c;
    c.sbase = sbase;
    c.tid  = threadIdx.x;
    c.lane = c.tid & 31;
    c.wid  = c.tid >> 5;
    c.warpM = c.wid & 1;
    c.warpN = c.wid >> 1;
    c.a_row = c.warpM * 64 + (c.lane & 15);
    c.a_kad = (c.lane >> 4) << 3;
    c.b_row = c.warpN * 32 + (c.lane & 7) + ((c.lane >> 4) << 3);
    c.b_kad = ((c.lane >> 3) & 1) << 3;
    return c;
}

template <bool BLO>
__device__ __forceinline__ void mainloop(
    const TileCtx& c, const __half* AH, const __half* BH, const __half* BL,
    int m0, int n0, int K, float acc[4][4][4])
{
    constexpr uint32_t ST_BH = MATB;
    constexpr uint32_t ST_BL = 2 * MATB;
    constexpr uint32_t STG   = (BLO ? 3 : 2) * MATB;

#pragma unroll
    for (int mi = 0; mi < 4; mi++)
#pragma unroll
        for (int ni = 0; ni < 4; ni++)
#pragma unroll
            for (int r = 0; r < 4; r++) acc[mi][ni][r] = 0.0f;

    auto fill = [&](int stg, int kt) {
        const int kc = kt * BK;
        const uint32_t sb = c.sbase + stg * STG;
#pragma unroll
        for (int j = 0; j < 2; j++) {
            const int idx = c.tid + NTH * j;
            const int r  = idx >> 2;
            const int ch = idx & 3;
            const uint32_t so = (uint32_t)(r * ROWB + ch * 16);
            cp16(sb + so,         AH + (size_t)(m0 + r) * K + kc + ch * 8);
            cp16(sb + ST_BH + so, BH + (size_t)(n0 + r) * K + kc + ch * 8);
            if (BLO) cp16(sb + ST_BL + so, BL + (size_t)(n0 + r) * K + kc + ch * 8);
        }
        CP_COMMIT();
    };

    const int KT = K / BK;
    fill(0, 0);
    fill(1, 1);

    for (int kt = 0; kt < KT; kt++) {
        if (kt == KT - 1) { CP_WAIT(0); } else { CP_WAIT(1); }
        __syncthreads();
        const uint32_t sb = c.sbase + (kt % NSTAGE) * STG;
        if (kt + NSTAGE - 1 < KT) fill((kt + NSTAGE - 1) % NSTAGE, kt + NSTAGE - 1);

#pragma unroll
        for (int ks = 0; ks < 2; ks++) {
            const int ko = ks * 16;
            uint32_t aH[4][4];
#pragma unroll
            for (int mi = 0; mi < 4; mi++) {
                const uint32_t ad = sb
                    + (uint32_t)((c.a_row + mi * 16) * ROWB + (ko + c.a_kad) * 2);
                ldsm4(aH[mi], ad);
            }
            uint32_t bHf[2][4], bLf[2][4];
#pragma unroll
            for (int nf = 0; nf < 2; nf++) {
                const uint32_t bd = sb + ST_BH
                    + (uint32_t)((c.b_row + nf * 16) * ROWB + (ko + c.b_kad) * 2);
                ldsm4(bHf[nf], bd);
                if (BLO) ldsm4(bLf[nf], bd + (ST_BL - ST_BH));
            }
#pragma unroll
            for (int mi = 0; mi < 4; mi++) {
#pragma unroll
                for (int ni = 0; ni < 4; ni++) {
                    const uint32_t* bh = &bHf[ni >> 1][(ni & 1) * 2];
                    mma16816(acc[mi][ni], aH[mi], bh[0], bh[1]);
                    if (BLO) {
                        const uint32_t* bl = &bLf[ni >> 1][(ni & 1) * 2];
                        mma16816(acc[mi][ni], aH[mi], bl[0], bl[1]);
                    }
                }
            }
        }
    }
}

// ============================================================================
// Fused projections: one launch, grid (12, 128).
//   z = blockIdx.x>>2:  0 -> Q (hi out),  1 -> K' (hi+lo out),
//                       2 -> V (hi out, transposed per batch)
// ============================================================================
__global__ __launch_bounds__(NTH, 2)
void proj3(const __half* __restrict__ xsh, const __half* __restrict__ xrh,
           const __half* __restrict__ wqh, const __half* __restrict__ wql,
           const __half* __restrict__ wkh, const __half* __restrict__ wkl,
           const __half* __restrict__ wvh, const __half* __restrict__ wvl,
           const float* __restrict__ bq, const float* __restrict__ bk,
           const float* __restrict__ bv, float sc,
           __half* __restrict__ qh,
           __half* __restrict__ kh, __half* __restrict__ kl,
           __half* __restrict__ vth)
{
    extern __shared__ char smem[];
    TileCtx c = make_ctx(smem_u32(smem));

    const int z  = blockIdx.x >> 2;
    const int n0 = (blockIdx.x & 3) * BN;
    const int m0 = blockIdx.y * BM;

    const __half* AH = (z == 1) ? xrh : xsh;
    const __half* BH = (z == 0) ? wqh : (z == 1) ? wkh : wvh;
    const __half* BL = (z == 0) ? wql : (z == 1) ? wkl : wvl;
    const float* bias = (z == 0) ? bq : (z == 1) ? bk : bv;
    const float alpha = (z == 0) ? sc : 1.0f;
    const float bcoef = (z == 0) ? sc : (z == 1) ? 2.0f : 1.0f;

    float acc[4][4][4];
    mainloop<true>(c, AH, BH, BL, m0, n0, HD, acc);

    const int rq = c.lane >> 2;
    const int cq = (c.lane & 3) * 2;

    if (z == 2) {
        // stage hi tile transposed in smem, then coalesced global writes
        __syncthreads();
        __half* bufh = (__half*)smem;
#pragma unroll
        for (int mi = 0; mi < 4; mi++) {
#pragma unroll
            for (int ni = 0; ni < 4; ni++) {
                const float* a4 = acc[mi][ni];
                const int lm = c.warpM * 64 + mi * 16 + rq;
                const int ln = c.warpN * 32 + ni * 8 + cq;
                const float b0 = bcoef * __ldg(&bias[n0 + ln]);
                const float b1 = bcoef * __ldg(&bias[n0 + ln + 1]);
#pragma unroll
                for (int h = 0; h < 2; h++) {
                    const int m = lm + h * 8;
                    bufh[ln * TSTR + m]       = __float2half(alpha * a4[2 * h]     + b0);
                    bufh[(ln + 1) * TSTR + m] = __float2half(alpha * a4[2 * h + 1] + b1);
                }
            }
        }
        __syncthreads();
        const int ncol = c.tid & 127;
        const int hhalf = c.tid >> 7;                    // which 64-row chunk
        const __half* src = bufh + ncol * TSTR + hhalf * 64;
        const int bb  = m0 >> 12;
        const int m0s = m0 & 4095;
        __half* dst = vth + ((size_t)bb * HD + n0 + ncol) * SEQ + m0s + hhalf * 64;
#pragma unroll
        for (int q = 0; q < 8; q++)
            ((uint4*)dst)[q] = ((const uint4*)src)[q];
        return;
    }

    const bool emit_lo = (z == 1);
    __half* O1 = (z == 0) ? qh : kh;
#pragma unroll
    for (int mi = 0; mi < 4; mi++) {
#pragma unroll
        for (int ni = 0; ni < 4; ni++) {
            const int mrow = m0 + c.warpM * 64 + mi * 16 + rq;
            const int ncol = n0 + c.warpN * 32 + ni * 8 + cq;
            const float* a4 = acc[mi][ni];
            const float b0 = bcoef * __ldg(&bias[ncol]);
            const float b1 = bcoef * __ldg(&bias[ncol + 1]);
#pragma unroll
            for (int h = 0; h < 2; h++) {
                const int m = mrow + h * 8;
                const float v0 = alpha * a4[2 * h]     + b0;
                const float v1 = alpha * a4[2 * h + 1] + b1;
                const __half h0 = __float2half(v0);
                const __half h1 = __float2half(v1);
                *(__half2*)(O1 + (size_t)m * HD + ncol) = __halves2half2(h0, h1);
                if (emit_lo) {
                    const __half l0 = __float2half(v0 - __half2float(h0));
                    const __half l1 = __float2half(v1 - __half2float(h1));
                    *(__half2*)(kl + (size_t)m * HD + ncol) = __halves2half2(l0, l1);
                }
            }
        }
    }
}

// ============================================================================
// Big GEMM: fp32 out, C[M,N] = A_hi[M,K] * B[N,K]^T  (QK: BLO, PV: !BLO)
// ============================================================================
template <bool BLO>
__global__ __launch_bounds__(NTH, 2)
void mma_big(const __half* __restrict__ AHg,
             const __half* __restrict__ BHg, const __half* __restrict__ BLg,
             float* __restrict__ Og,
             int N, int K, size_t sA, size_t sB, size_t sO)
{
    extern __shared__ char smem[];
    TileCtx c = make_ctx(smem_u32(smem));

    const int m0 = blockIdx.y * BM;
    const int n0 = blockIdx.x * BN;
    const __half* AH = AHg + (size_t)blockIdx.z * sA;
    const __half* BH = BHg + (size_t)blockIdx.z * sB;
    const __half* BL = BLO ? (BLg + (size_t)blockIdx.z * sB) : (const __half*)0;
    float* O = Og + (size_t)blockIdx.z * sO;

    float acc[4][4][4];
    mainloop<BLO>(c, AH, BH, BL, m0, n0, K, acc);

    const int rq = c.lane >> 2;
    const int cq = (c.lane & 3) * 2;
#pragma unroll
    for (int mi = 0; mi < 4; mi++) {
#pragma unroll
        for (int ni = 0; ni < 4; ni++) {
            const int mrow = m0 + c.warpM * 64 + mi * 16 + rq;
            const int ncol = n0 + c.warpN * 32 + ni * 8 + cq;
            const float* a4 = acc[mi][ni];
            *(float2*)(O + (size_t)mrow * N + ncol)       = make_float2(a4[0], a4[1]);
            *(float2*)(O + (size_t)(mrow + 8) * N + ncol) = make_float2(a4[2], a4[3]);
        }
    }
}

// ============================================================================
// split kernels
// ============================================================================
__global__ void split_x(const float* __restrict__ x, const float* __restrict__ rp,
                        __half* __restrict__ xsh, __half* __restrict__ xrh)
{
    const int z = blockIdx.z;
    const int i = (blockIdx.x * blockDim.x + threadIdx.x) * 4;
    float4 v = *(const float4*)(x + i);
    if (z) {
        const float4 u = *(const float4*)(rp + i);
        v.x += u.x; v.y += u.y; v.z += u.z; v.w += u.w;
    }
    __half* hi = z ? xrh : xsh;
    *(__half2*)(hi + i)     = __halves2half2(__float2half(v.x), __float2half(v.y));
    *(__half2*)(hi + i + 2) = __halves2half2(__float2half(v.z), __float2half(v.w));
}

__global__ void split_w(const float* __restrict__ w0, const float* __restrict__ w1,
                        const float* __restrict__ w2,
                        __half* __restrict__ h0p, __half* __restrict__ l0p,
                        __half* __restrict__ h1p, __half* __restrict__ l1p,
                        __half* __restrict__ h2p, __half* __restrict__ l2p)
{
    const int z = blockIdx.z;
    const float* a = (z == 0) ? w0 : (z == 1) ? w1 : w2;
    __half* hi = (z == 0) ? h0p : (z == 1) ? h1p : h2p;
    __half* lo = (z == 0) ? l0p : (z == 1) ? l1p : l2p;
    const int i = (blockIdx.x * blockDim.x + threadIdx.x) * 4;
    const float4 v = *(const float4*)(a + i);
    const __half h0 = __float2half(v.x), h1 = __float2half(v.y);
    const __half h2 = __float2half(v.z), h3 = __float2half(v.w);
    *(__half2*)(hi + i)     = __halves2half2(h0, h1);
    *(__half2*)(hi + i + 2) = __halves2half2(h2, h3);
    *(__half2*)(lo + i)     = __halves2half2(__float2half(v.x - __half2float(h0)),
                                             __float2half(v.y - __half2float(h1)));
    *(__half2*)(lo + i + 2) = __halves2half2(__float2half(v.z - __half2float(h2)),
                                             __float2half(v.w - __half2float(h3)));
}

// ============================================================================
// Row softmax over n=4096, emits P as fp16 (hi only).
// ============================================================================
__global__ void softmax_rows(const float* __restrict__ S, __half* __restrict__ ph)
{
    const int n = 4096;
    const size_t base = (size_t)blockIdx.x * n;
    const float* p = S + base;
    const int t = threadIdx.x;

    float4 v[4];
#pragma unroll
    for (int i = 0; i < 4; i++) v[i] = *(const float4*)(p + (size_t)(i * 256 + t) * 4);

    __shared__ float redm[8];
    __shared__ float reds[8];

    float mx = -3.4e38f;
#pragma unroll
    for (int i = 0; i < 4; i++)
        mx = fmaxf(mx, fmaxf(fmaxf(v[i].x, v[i].y), fmaxf(v[i].z, v[i].w)));
#pragma unroll
    for (int o = 16; o; o >>= 1) mx = fmaxf(mx, __shfl_xor_sync(0xffffffffu, mx, o));
    if ((t & 31) == 0) redm[t >> 5] = mx;
    __syncthreads();
    float m = redm[0];
#pragma unroll
    for (int i = 1; i < 8; i++) m = fmaxf(m, redm[i]);

    float sum = 0.0f;
#pragma unroll
    for (int i = 0; i < 4; i++) {
        v[i].x = __expf(v[i].x - m);
        v[i].y = __expf(v[i].y - m);
        v[i].z = __expf(v[i].z - m);
        v[i].w = __expf(v[i].w - m);
        sum += (v[i].x + v[i].y) + (v[i].z + v[i].w);
    }
#pragma unroll
    for (int o = 16; o; o >>= 1) sum += __shfl_xor_sync(0xffffffffu, sum, o);
    if ((t & 31) == 0) reds[t >> 5] = sum;
    __syncthreads();
    float stot = 0.0f;
#pragma unroll
    for (int i = 0; i < 8; i++) stot += reds[i];
    const float inv = 1.0f / stot;

#pragma unroll
    for (int i = 0; i < 4; i++) {
        const int idx = (i * 256 + t) * 4;
        *(__half2*)(ph + base + idx)     = __halves2half2(__float2half(v[i].x * inv),
                                                          __float2half(v[i].y * inv));
        *(__half2*)(ph + base + idx + 2) = __halves2half2(__float2half(v[i].z * inv),
                                                          __float2half(v[i].w * inv));
    }
}

// ============================================================================
// kernel_launch
// ============================================================================
extern "C" void kernel_launch(void* const* d_in, const int* in_sizes, int n_in,
                              void* d_out, int out_size)
{
    (void)in_sizes; (void)n_in; (void)out_size;
    const float* x  = (const float*)d_in[0];
    const float* rp = (const float*)d_in[1];
    const float* Wq = (const float*)d_in[2];
    const float* bq = (const float*)d_in[3];
    const float* Wk = (const float*)d_in[4];
    const float* bk = (const float*)d_in[5];
    const float* Wv = (const float*)d_in[6];
    const float* bv = (const float*)d_in[7];
    float* out = (float*)d_out;

    __half *xsh, *xrh, *wqh, *wql, *wkh, *wkl, *wvh, *wvl;
    __half *qh, *kh, *kl, *vth, *ph;
    float* S;
    cudaGetSymbolAddress((void**)&xsh, g_xsh);
    cudaGetSymbolAddress((void**)&xrh, g_xrh);
    cudaGetSymbolAddress((void**)&wqh, g_wqh); cudaGetSymbolAddress((void**)&wql, g_wql);
    cudaGetSymbolAddress((void**)&wkh, g_wkh); cudaGetSymbolAddress((void**)&wkl, g_wkl);
    cudaGetSymbolAddress((void**)&wvh, g_wvh); cudaGetSymbolAddress((void**)&wvl, g_wvl);
    cudaGetSymbolAddress((void**)&qh,  g_qh);
    cudaGetSymbolAddress((void**)&kh,  g_kh);  cudaGetSymbolAddress((void**)&kl,  g_kl);
    cudaGetSymbolAddress((void**)&vth, g_vth);
    cudaGetSymbolAddress((void**)&ph,  g_ph);
    cudaGetSymbolAddress((void**)&S,   g_S);

    cudaFuncSetAttribute((const void*)proj3,
                         cudaFuncAttributeMaxDynamicSharedMemorySize, SMEM_B3);
    cudaFuncSetAttribute((const void*)mma_big<true>,
                         cudaFuncAttributeMaxDynamicSharedMemorySize, SMEM_B3);
    cudaFuncSetAttribute((const void*)mma_big<false>,
                         cudaFuncAttributeMaxDynamicSharedMemorySize, SMEM_B2);

    const float sc = (float)(1.0 / sqrt((double)HD));

    // --- splits (2 launches) ---
    split_x<<<dim3(TOK * HD / 1024, 1, 2), 256>>>(x, rp, xsh, xrh);
    split_w<<<dim3(HD * HD / 1024, 1, 3), 256>>>(Wq, Wk, Wv,
                                                 wqh, wql, wkh, wkl, wvh, wvl);

    // --- fused projections: Q | K' | V(transposed, hi only), one launch ---
    proj3<<<dim3(12, TOK / BM), NTH, SMEM_B3>>>(
        xsh, xrh, wqh, wql, wkh, wkl, wvh, wvl,
        bq, bk, bv, sc, qh, kh, kl, vth);

    // --- scores, all batches in one launch (tail amortized) ---
    mma_big<true><<<dim3(SEQ / BN, SEQ / BM, NB), NTH, SMEM_B3>>>(
        qh, kh, kl, S,
        SEQ, HD, (size_t)SEQ * HD, (size_t)SEQ * HD, (size_t)SEQ * SEQ);

    // --- softmax, all batches in one launch ---
    softmax_rows<<<NB * SEQ, 256>>>(S, ph);

    // --- out: O[b] = Ph[b] · Vt_hi[b]^T (1-MMA plain fp16) ---
    mma_big<false><<<dim3(HD / BN, SEQ / BM, NB), NTH, SMEM_B2>>>(
        ph, vth, (const __half*)0, out,
        HD, SEQ, (size_t)SEQ * SEQ, (size_t)HD * SEQ, (size_t)SEQ * HD);
}

// round 11
// speedup vs baseline: 5.4566x; 1.2430x over previous
#include <cuda_runtime.h>
#include <cuda_fp16.h>
#include <math.h>
#include <stdint.h>

// ============================================================================
// ResponseAttention via mma.sync (m16n8k16 fp16), asymmetric Ozaki split.
//   scores = Qs · K'^T, Qs=(x·Wq^T+bq)/sqrt(H), K'=(x+rp)·Wk^T+2bk
//   out    = softmax(scores) · V   (V stored transposed so P·V is NT too)
// Projections: 2-MMA split on the WEIGHT side only (W = hi+lo; x fp16-hi).
// Big GEMMs (QK, PV): plain 1-MMA fp16 with fp32 accumulate — Q/K'/P/V
// truncation errors accumulate sub-quadrature to ~5.5e-4 < 1e-3 gate.
// R11: dropped K'_lo (QK 377us @ tensor 62% was the last 2-MMA big GEMM).
// tcgen05 unavailable (compute_103 virtual arch) — mma.sync is the path.
// B=4, S=4096, H=512.
// ============================================================================

#define BM 128
#define BN 128
#define BK 32
#define NSTAGE 3
#define NTH 256

#define TOK 16384
#define HD  512
#define SEQ 4096
#define NB  4

// smem: rows of 32 fp16 padded to 40 (80 B) -> conflict-free ldmatrix
#define ROWB 80
#define MATB (128 * ROWB)                       // one 128x32 fp16 matrix: 10240 B
#define SMEM_B3 (NSTAGE * 3 * MATB)             // 92160 (A BH BL) - projections
#define SMEM_B2 (NSTAGE * 2 * MATB)             // 61440 (A BH)    - big GEMMs

#define TSTR 136                                // transpose-buffer row stride (halves)

// ---------------------------- scratch ------------------------------------
__device__ __half g_xsh[TOK * HD];
__device__ __half g_xrh[TOK * HD];
__device__ __half g_wqh[HD * HD], g_wql[HD * HD];
__device__ __half g_wkh[HD * HD], g_wkl[HD * HD];
__device__ __half g_wvh[HD * HD], g_wvl[HD * HD];
__device__ __half g_qh[TOK * HD];
__device__ __half g_kh[TOK * HD];
__device__ __half g_vth[TOK * HD];
__device__ float  g_S[(size_t)NB * SEQ * SEQ];
__device__ __half g_ph[(size_t)NB * SEQ * SEQ];

// ---------------------------- helpers ------------------------------------
__device__ __forceinline__ uint32_t smem_u32(const void* p) {
    uint32_t a;
    asm("{ .reg .u64 t; cvta.to.shared.u64 t, %1; cvt.u32.u64 %0, t; }"
        : "=r"(a) : "l"(p));
    return a;
}
__device__ __forceinline__ void cp16(uint32_t s, const void* g) {
    asm volatile("cp.async.cg.shared.global [%0], [%1], 16;" :: "r"(s), "l"(g));
}
#define CP_COMMIT() asm volatile("cp.async.commit_group;")
#define CP_WAIT(n)  asm volatile("cp.async.wait_group %0;" :: "n"(n))

__device__ __forceinline__ void ldsm4(uint32_t r[4], uint32_t addr) {
    asm volatile("ldmatrix.sync.aligned.m8n8.x4.shared.b16 {%0,%1,%2,%3}, [%4];"
        : "=r"(r[0]), "=r"(r[1]), "=r"(r[2]), "=r"(r[3]) : "r"(addr));
}
__device__ __forceinline__ void mma16816(float acc[4], const uint32_t a[4],
                                         const uint32_t b0, const uint32_t b1) {
    asm volatile(
        "mma.sync.aligned.m16n8k16.row.col.f32.f16.f16.f32 "
        "{%0,%1,%2,%3}, {%4,%5,%6,%7}, {%8,%9}, {%0,%1,%2,%3};"
        : "+f"(acc[0]), "+f"(acc[1]), "+f"(acc[2]), "+f"(acc[3])
        : "r"(a[0]), "r"(a[1]), "r"(a[2]), "r"(a[3]), "r"(b0), "r"(b1));
}

// ---------------------------------------------------------------------------
// Shared mainloop: C[128,128] tile of A_hi[M,K] * B[N,K]^T.
//   BLO=true : B = (hi, lo), 2 MMAs per fragment
//   BLO=false: B = hi only,  1 MMA per fragment
// acc[4][4][4], 8 warps (2M x 4N), 3-stage cp.async pipeline.
// ---------------------------------------------------------------------------
struct TileCtx {
    uint32_t sbase;
    int tid, lane, wid, warpM, warpN;
    int a_row, a_kad, b_row, b_kad;
};

__device__ __forceinline__ TileCtx make_ctx(uint32_t sbase) {
    TileCtx c;
    c.sbase = sbase;
    c.tid  = threadIdx.x;
    c.lane = c.tid & 31;
    c.wid  = c.tid >> 5;
    c.warpM = c.wid & 1;
    c.warpN = c.wid >> 1;
    c.a_row = c.warpM * 64 + (c.lane & 15);
    c.a_kad = (c.lane >> 4) << 3;
    c.b_row = c.warpN * 32 + (c.lane & 7) + ((c.lane >> 4) << 3);
    c.b_kad = ((c.lane >> 3) & 1) << 3;
    return c;
}

template <bool BLO>
__device__ __forceinline__ void mainloop(
    const TileCtx& c, const __half* AH, const __half* BH, const __half* BL,
    int m0, int n0, int K, float acc[4][4][4])
{
    constexpr uint32_t ST_BH = MATB;
    constexpr uint32_t ST_BL = 2 * MATB;
    constexpr uint32_t STG   = (BLO ? 3 : 2) * MATB;

#pragma unroll
    for (int mi = 0; mi < 4; mi++)
#pragma unroll
        for (int ni = 0; ni < 4; ni++)
#pragma unroll
            for (int r = 0; r < 4; r++) acc[mi][ni][r] = 0.0f;

    auto fill = [&](int stg, int kt) {
        const int kc = kt * BK;
        const uint32_t sb = c.sbase + stg * STG;
#pragma unroll
        for (int j = 0; j < 2; j++) {
            const int idx = c.tid + NTH * j;
            const int r  = idx >> 2;
            const int ch = idx & 3;
            const uint32_t so = (uint32_t)(r * ROWB + ch * 16);
            cp16(sb + so,         AH + (size_t)(m0 + r) * K + kc + ch * 8);
            cp16(sb + ST_BH + so, BH + (size_t)(n0 + r) * K + kc + ch * 8);
            if (BLO) cp16(sb + ST_BL + so, BL + (size_t)(n0 + r) * K + kc + ch * 8);
        }
        CP_COMMIT();
    };

    const int KT = K / BK;
    fill(0, 0);
    fill(1, 1);

    for (int kt = 0; kt < KT; kt++) {
        if (kt == KT - 1) { CP_WAIT(0); } else { CP_WAIT(1); }
        __syncthreads();
        const uint32_t sb = c.sbase + (kt % NSTAGE) * STG;
        if (kt + NSTAGE - 1 < KT) fill((kt + NSTAGE - 1) % NSTAGE, kt + NSTAGE - 1);

#pragma unroll
        for (int ks = 0; ks < 2; ks++) {
            const int ko = ks * 16;
            uint32_t aH[4][4];
#pragma unroll
            for (int mi = 0; mi < 4; mi++) {
                const uint32_t ad = sb
                    + (uint32_t)((c.a_row + mi * 16) * ROWB + (ko + c.a_kad) * 2);
                ldsm4(aH[mi], ad);
            }
            uint32_t bHf[2][4], bLf[2][4];
#pragma unroll
            for (int nf = 0; nf < 2; nf++) {
                const uint32_t bd = sb + ST_BH
                    + (uint32_t)((c.b_row + nf * 16) * ROWB + (ko + c.b_kad) * 2);
                ldsm4(bHf[nf], bd);
                if (BLO) ldsm4(bLf[nf], bd + (ST_BL - ST_BH));
            }
#pragma unroll
            for (int mi = 0; mi < 4; mi++) {
#pragma unroll
                for (int ni = 0; ni < 4; ni++) {
                    const uint32_t* bh = &bHf[ni >> 1][(ni & 1) * 2];
                    mma16816(acc[mi][ni], aH[mi], bh[0], bh[1]);
                    if (BLO) {
                        const uint32_t* bl = &bLf[ni >> 1][(ni & 1) * 2];
                        mma16816(acc[mi][ni], aH[mi], bl[0], bl[1]);
                    }
                }
            }
        }
    }
}

// ============================================================================
// Fused projections: one launch, grid (12, 128). All outputs fp16-hi only.
//   z = blockIdx.x>>2:  0 -> Q,  1 -> K',  2 -> V (transposed per batch)
// ============================================================================
__global__ __launch_bounds__(NTH, 2)
void proj3(const __half* __restrict__ xsh, const __half* __restrict__ xrh,
           const __half* __restrict__ wqh, const __half* __restrict__ wql,
           const __half* __restrict__ wkh, const __half* __restrict__ wkl,
           const __half* __restrict__ wvh, const __half* __restrict__ wvl,
           const float* __restrict__ bq, const float* __restrict__ bk,
           const float* __restrict__ bv, float sc,
           __half* __restrict__ qh, __half* __restrict__ kh,
           __half* __restrict__ vth)
{
    extern __shared__ char smem[];
    TileCtx c = make_ctx(smem_u32(smem));

    const int z  = blockIdx.x >> 2;
    const int n0 = (blockIdx.x & 3) * BN;
    const int m0 = blockIdx.y * BM;

    const __half* AH = (z == 1) ? xrh : xsh;
    const __half* BH = (z == 0) ? wqh : (z == 1) ? wkh : wvh;
    const __half* BL = (z == 0) ? wql : (z == 1) ? wkl : wvl;
    const float* bias = (z == 0) ? bq : (z == 1) ? bk : bv;
    const float alpha = (z == 0) ? sc : 1.0f;
    const float bcoef = (z == 0) ? sc : (z == 1) ? 2.0f : 1.0f;

    float acc[4][4][4];
    mainloop<true>(c, AH, BH, BL, m0, n0, HD, acc);

    const int rq = c.lane >> 2;
    const int cq = (c.lane & 3) * 2;

    if (z == 2) {
        // stage hi tile transposed in smem, then coalesced global writes
        __syncthreads();
        __half* bufh = (__half*)smem;
#pragma unroll
        for (int mi = 0; mi < 4; mi++) {
#pragma unroll
            for (int ni = 0; ni < 4; ni++) {
                const float* a4 = acc[mi][ni];
                const int lm = c.warpM * 64 + mi * 16 + rq;
                const int ln = c.warpN * 32 + ni * 8 + cq;
                const float b0 = bcoef * __ldg(&bias[n0 + ln]);
                const float b1 = bcoef * __ldg(&bias[n0 + ln + 1]);
#pragma unroll
                for (int h = 0; h < 2; h++) {
                    const int m = lm + h * 8;
                    bufh[ln * TSTR + m]       = __float2half(alpha * a4[2 * h]     + b0);
                    bufh[(ln + 1) * TSTR + m] = __float2half(alpha * a4[2 * h + 1] + b1);
                }
            }
        }
        __syncthreads();
        const int ncol = c.tid & 127;
        const int hhalf = c.tid >> 7;                    // which 64-row chunk
        const __half* src = bufh + ncol * TSTR + hhalf * 64;
        const int bb  = m0 >> 12;
        const int m0s = m0 & 4095;
        __half* dst = vth + ((size_t)bb * HD + n0 + ncol) * SEQ + m0s + hhalf * 64;
#pragma unroll
        for (int q = 0; q < 8; q++)
            ((uint4*)dst)[q] = ((const uint4*)src)[q];
        return;
    }

    __half* O1 = (z == 0) ? qh : kh;
#pragma unroll
    for (int mi = 0; mi < 4; mi++) {
#pragma unroll
        for (int ni = 0; ni < 4; ni++) {
            const int mrow = m0 + c.warpM * 64 + mi * 16 + rq;
            const int ncol = n0 + c.warpN * 32 + ni * 8 + cq;
            const float* a4 = acc[mi][ni];
            const float b0 = bcoef * __ldg(&bias[ncol]);
            const float b1 = bcoef * __ldg(&bias[ncol + 1]);
#pragma unroll
            for (int h = 0; h < 2; h++) {
                const int m = mrow + h * 8;
                const __half h0 = __float2half(alpha * a4[2 * h]     + b0);
                const __half h1 = __float2half(alpha * a4[2 * h + 1] + b1);
                *(__half2*)(O1 + (size_t)m * HD + ncol) = __halves2half2(h0, h1);
            }
        }
    }
}

// ============================================================================
// Big GEMM: fp32 out, C[M,N] = A_hi[M,K] * B_hi[N,K]^T  (QK and PV, 1-MMA)
// ============================================================================
__global__ __launch_bounds__(NTH, 2)
void mma_big(const __half* __restrict__ AHg, const __half* __restrict__ BHg,
             float* __restrict__ Og,
             int N, int K, size_t sA, size_t sB, size_t sO)
{
    extern __shared__ char smem[];
    TileCtx c = make_ctx(smem_u32(smem));

    const int m0 = blockIdx.y * BM;
    const int n0 = blockIdx.x * BN;
    const __half* AH = AHg + (size_t)blockIdx.z * sA;
    const __half* BH = BHg + (size_t)blockIdx.z * sB;
    float* O = Og + (size_t)blockIdx.z * sO;

    float acc[4][4][4];
    mainloop<false>(c, AH, BH, (const __half*)0, m0, n0, K, acc);

    const int rq = c.lane >> 2;
    const int cq = (c.lane & 3) * 2;
#pragma unroll
    for (int mi = 0; mi < 4; mi++) {
#pragma unroll
        for (int ni = 0; ni < 4; ni++) {
            const int mrow = m0 + c.warpM * 64 + mi * 16 + rq;
            const int ncol = n0 + c.warpN * 32 + ni * 8 + cq;
            const float* a4 = acc[mi][ni];
            *(float2*)(O + (size_t)mrow * N + ncol)       = make_float2(a4[0], a4[1]);
            *(float2*)(O + (size_t)(mrow + 8) * N + ncol) = make_float2(a4[2], a4[3]);
        }
    }
}

// ============================================================================
// split kernels
// ============================================================================
__global__ void split_x(const float* __restrict__ x, const float* __restrict__ rp,
                        __half* __restrict__ xsh, __half* __restrict__ xrh)
{
    const int z = blockIdx.z;
    const int i = (blockIdx.x * blockDim.x + threadIdx.x) * 4;
    float4 v = *(const float4*)(x + i);
    if (z) {
        const float4 u = *(const float4*)(rp + i);
        v.x += u.x; v.y += u.y; v.z += u.z; v.w += u.w;
    }
    __half* hi = z ? xrh : xsh;
    *(__half2*)(hi + i)     = __halves2half2(__float2half(v.x), __float2half(v.y));
    *(__half2*)(hi + i + 2) = __halves2half2(__float2half(v.z), __float2half(v.w));
}

__global__ void split_w(const float* __restrict__ w0, const float* __restrict__ w1,
                        const float* __restrict__ w2,
                        __half* __restrict__ h0p, __half* __restrict__ l0p,
                        __half* __restrict__ h1p, __half* __restrict__ l1p,
                        __half* __restrict__ h2p, __half* __restrict__ l2p)
{
    const int z = blockIdx.z;
    const float* a = (z == 0) ? w0 : (z == 1) ? w1 : w2;
    __half* hi = (z == 0) ? h0p : (z == 1) ? h1p : h2p;
    __half* lo = (z == 0) ? l0p : (z == 1) ? l1p : l2p;
    const int i = (blockIdx.x * blockDim.x + threadIdx.x) * 4;
    const float4 v = *(const float4*)(a + i);
    const __half h0 = __float2half(v.x), h1 = __float2half(v.y);
    const __half h2 = __float2half(v.z), h3 = __float2half(v.w);
    *(__half2*)(hi + i)     = __halves2half2(h0, h1);
    *(__half2*)(hi + i + 2) = __halves2half2(h2, h3);
    *(__half2*)(lo + i)     = __halves2half2(__float2half(v.x - __half2float(h0)),
                                             __float2half(v.y - __half2float(h1)));
    *(__half2*)(lo + i + 2) = __halves2half2(__float2half(v.z - __half2float(h2)),
                                             __float2half(v.w - __half2float(h3)));
}

// ============================================================================
// Row softmax over n=4096, emits P as fp16 (hi only).
// ============================================================================
__global__ void softmax_rows(const float* __restrict__ S, __half* __restrict__ ph)
{
    const int n = 4096;
    const size_t base = (size_t)blockIdx.x * n;
    const float* p = S + base;
    const int t = threadIdx.x;

    float4 v[4];
#pragma unroll
    for (int i = 0; i < 4; i++) v[i] = *(const float4*)(p + (size_t)(i * 256 + t) * 4);

    __shared__ float redm[8];
    __shared__ float reds[8];

    float mx = -3.4e38f;
#pragma unroll
    for (int i = 0; i < 4; i++)
        mx = fmaxf(mx, fmaxf(fmaxf(v[i].x, v[i].y), fmaxf(v[i].z, v[i].w)));
#pragma unroll
    for (int o = 16; o; o >>= 1) mx = fmaxf(mx, __shfl_xor_sync(0xffffffffu, mx, o));
    if ((t & 31) == 0) redm[t >> 5] = mx;
    __syncthreads();
    float m = redm[0];
#pragma unroll
    for (int i = 1; i < 8; i++) m = fmaxf(m, redm[i]);

    float sum = 0.0f;
#pragma unroll
    for (int i = 0; i < 4; i++) {
        v[i].x = __expf(v[i].x - m);
        v[i].y = __expf(v[i].y - m);
        v[i].z = __expf(v[i].z - m);
        v[i].w = __expf(v[i].w - m);
        sum += (v[i].x + v[i].y) + (v[i].z + v[i].w);
    }
#pragma unroll
    for (int o = 16; o; o >>= 1) sum += __shfl_xor_sync(0xffffffffu, sum, o);
    if ((t & 31) == 0) reds[t >> 5] = sum;
    __syncthreads();
    float stot = 0.0f;
#pragma unroll
    for (int i = 0; i < 8; i++) stot += reds[i];
    const float inv = 1.0f / stot;

#pragma unroll
    for (int i = 0; i < 4; i++) {
        const int idx = (i * 256 + t) * 4;
        *(__half2*)(ph + base + idx)     = __halves2half2(__float2half(v[i].x * inv),
                                                          __float2half(v[i].y * inv));
        *(__half2*)(ph + base + idx + 2) = __halves2half2(__float2half(v[i].z * inv),
                                                          __float2half(v[i].w * inv));
    }
}

// ============================================================================
// kernel_launch
// ============================================================================
extern "C" void kernel_launch(void* const* d_in, const int* in_sizes, int n_in,
                              void* d_out, int out_size)
{
    (void)in_sizes; (void)n_in; (void)out_size;
    const float* x  = (const float*)d_in[0];
    const float* rp = (const float*)d_in[1];
    const float* Wq = (const float*)d_in[2];
    const float* bq = (const float*)d_in[3];
    const float* Wk = (const float*)d_in[4];
    const float* bk = (const float*)d_in[5];
    const float* Wv = (const float*)d_in[6];
    const float* bv = (const float*)d_in[7];
    float* out = (float*)d_out;

    __half *xsh, *xrh, *wqh, *wql, *wkh, *wkl, *wvh, *wvl;
    __half *qh, *kh, *vth, *ph;
    float* S;
    cudaGetSymbolAddress((void**)&xsh, g_xsh);
    cudaGetSymbolAddress((void**)&xrh, g_xrh);
    cudaGetSymbolAddress((void**)&wqh, g_wqh); cudaGetSymbolAddress((void**)&wql, g_wql);
    cudaGetSymbolAddress((void**)&wkh, g_wkh); cudaGetSymbolAddress((void**)&wkl, g_wkl);
    cudaGetSymbolAddress((void**)&wvh, g_wvh); cudaGetSymbolAddress((void**)&wvl, g_wvl);
    cudaGetSymbolAddress((void**)&qh,  g_qh);
    cudaGetSymbolAddress((void**)&kh,  g_kh);
    cudaGetSymbolAddress((void**)&vth, g_vth);
    cudaGetSymbolAddress((void**)&ph,  g_ph);
    cudaGetSymbolAddress((void**)&S,   g_S);

    cudaFuncSetAttribute((const void*)proj3,
                         cudaFuncAttributeMaxDynamicSharedMemorySize, SMEM_B3);
    cudaFuncSetAttribute((const void*)mma_big,
                         cudaFuncAttributeMaxDynamicSharedMemorySize, SMEM_B2);

    const float sc = (float)(1.0 / sqrt((double)HD));

    // --- splits (2 launches) ---
    split_x<<<dim3(TOK * HD / 1024, 1, 2), 256>>>(x, rp, xsh, xrh);
    split_w<<<dim3(HD * HD / 1024, 1, 3), 256>>>(Wq, Wk, Wv,
                                                 wqh, wql, wkh, wkl, wvh, wvl);

    // --- fused projections: Q | K' | V(transposed), one launch, hi outputs ---
    proj3<<<dim3(12, TOK / BM), NTH, SMEM_B3>>>(
        xsh, xrh, wqh, wql, wkh, wkl, wvh, wvl,
        bq, bk, bv, sc, qh, kh, vth);

    // --- scores: S[b] = Qh[b] · K'h[b]^T (1-MMA fp16, fp32 accum) ---
    mma_big<<<dim3(SEQ / BN, SEQ / BM, NB), NTH, SMEM_B2>>>(
        qh, kh, S,
        SEQ, HD, (size_t)SEQ * HD, (size_t)SEQ * HD, (size_t)SEQ * SEQ);

    // --- softmax, all batches in one launch ---
    softmax_rows<<<NB * SEQ, 256>>>(S, ph);

    // --- out: O[b] = Ph[b] · Vt_h[b]^T (1-MMA fp16, fp32 accum) ---
    mma_big<<<dim3(HD / BN, SEQ / BM, NB), NTH, SMEM_B2>>>(
        ph, vth, out,
        HD, SEQ, (size_t)SEQ * SEQ, (size_t)HD * SEQ, (size_t)SEQ * HD);
}